// round 2
// baseline (speedup 1.0000x reference)
#include <cuda_runtime.h>
#include <cuda_bf16.h>
#include <stdint.h>

#define NN 50000
#define NE 800000
#define INF 128
#define HID 64

// ---------------- scratch (static device memory; no allocations) ----------------
// fbuf layout: [0]=fo0 [1]=fo1 [2]=fo2 [3]=fs0 [4]=fs1 [5]=fs2 [6]=ga [7]=gb
__device__ float d_fbuf[(size_t)8 * NN * HID];
__device__ float d_dinv[2 * NN];
__device__ int   d_cnt [2 * NN];
__device__ int   d_cur [2 * NN];
__device__ int   d_rs  [2 * (NN + 1)];
__device__ int   d_csr [2 * NE];

// ---------------- degree histogram ----------------
__global__ void count_k(const int* __restrict__ dst, int* __restrict__ cnt, int ne) {
    int i = blockIdx.x * blockDim.x + threadIdx.x;
    if (i < ne) atomicAdd(&cnt[dst[i]], 1);
}

// ---------------- exclusive scan + dinv (one block per branch) ----------------
__global__ void scan_k(const int* __restrict__ cnt0, int* __restrict__ rs0, float* __restrict__ dv0,
                       const int* __restrict__ cnt1, int* __restrict__ rs1, float* __restrict__ dv1,
                       int n) {
    const int* cnt = blockIdx.x ? cnt1 : cnt0;
    int*       rs  = blockIdx.x ? rs1  : rs0;
    float*     dv  = blockIdx.x ? dv1  : dv0;
    __shared__ int wsum[32];
    __shared__ int carry_s;
    int tid = threadIdx.x, lane = tid & 31, wid = tid >> 5;
    if (tid == 0) carry_s = 0;
    __syncthreads();
    for (int base = 0; base < n; base += 1024) {
        int i = base + tid;
        int v = (i < n) ? cnt[i] : 0;
        int x = v;
        #pragma unroll
        for (int d = 1; d < 32; d <<= 1) {
            int t = __shfl_up_sync(0xffffffffu, x, d);
            if (lane >= d) x += t;
        }
        if (lane == 31) wsum[wid] = x;
        __syncthreads();
        if (wid == 0) {
            int w = wsum[lane];
            int y = w;
            #pragma unroll
            for (int d = 1; d < 32; d <<= 1) {
                int t = __shfl_up_sync(0xffffffffu, y, d);
                if (lane >= d) y += t;
            }
            wsum[lane] = y - w;  // exclusive warp offsets
        }
        __syncthreads();
        int excl = x - v + wsum[wid] + carry_s;
        if (i < n) {
            rs[i] = excl;
            dv[i] = rsqrtf((float)(v > 0 ? v : 1));
        }
        __syncthreads();
        if (tid == 1023) carry_s = excl + v;
        __syncthreads();
    }
    if (threadIdx.x == 0) rs[n] = carry_s;
}

// ---------------- CSR fill ----------------
__global__ void fill_k(const int* __restrict__ src, const int* __restrict__ dst,
                       const int* __restrict__ rs, int* __restrict__ cur,
                       int* __restrict__ csr, int ne) {
    int i = blockIdx.x * blockDim.x + threadIdx.x;
    if (i < ne) {
        int d = dst[i];
        int p = rs[d] + atomicAdd(&cur[d], 1);
        csr[p] = src[i];
    }
}

// ---------------- input GEMM + relu: H[n,64] = relu(X[n,128] @ W[128,64] + b) ----------------
__global__ void gemm_relu_k(const float* __restrict__ X, const float* __restrict__ W,
                            const float* __restrict__ b, float* __restrict__ H, int n) {
    __shared__ float Ws[INF * HID];   // 32 KB
    __shared__ float Xs[32 * INF];    // 16 KB
    int tid = threadIdx.x;
    int col = tid & 63, grp = tid >> 6;
    int nb = blockIdx.x * 32;
    for (int i = tid; i < INF * HID; i += 256) Ws[i] = W[i];
    int lim = (n - nb) * INF;
    if (lim > 32 * INF) lim = 32 * INF;
    for (int i = tid; i < 32 * INF; i += 256)
        Xs[i] = (i < lim) ? X[(size_t)nb * INF + i] : 0.f;
    __syncthreads();
    float acc[8] = {0, 0, 0, 0, 0, 0, 0, 0};
    #pragma unroll 8
    for (int k = 0; k < INF; k++) {
        float w = Ws[k * HID + col];
        #pragma unroll
        for (int j = 0; j < 8; j++) acc[j] += Xs[(grp * 8 + j) * INF + k] * w;
    }
    float bb = b[col];
    #pragma unroll
    for (int j = 0; j < 8; j++) {
        int node = nb + grp * 8 + j;
        if (node < n) {
            float v = acc[j] + bb;
            H[(size_t)node * HID + col] = v > 0.f ? v : 0.f;
        }
    }
}

// ---------------- g = f * dinv ----------------
__global__ void scale_k(const float4* __restrict__ f, const float* __restrict__ dinv,
                        float4* __restrict__ g, int n) {
    int i = blockIdx.x * blockDim.x + threadIdx.x;
    if (i < n * 16) {
        float4 v = f[i];
        float dv = dinv[i >> 4];
        v.x *= dv; v.y *= dv; v.z *= dv; v.w *= dv;
        g[i] = v;
    }
}

// ---------------- propagation step (gather): fout = f - dinv * sum_{src in N(v)} g[src] ----------------
// Also emits gout = fout * dinv for the next step (if non-null).
__global__ void prop_k(const float* __restrict__ g, const float* __restrict__ f,
                       const float* __restrict__ dinv,
                       const int* __restrict__ rs, const int* __restrict__ csr,
                       float* __restrict__ fout, float* __restrict__ gout, int n) {
    int w = (blockIdx.x * blockDim.x + threadIdx.x) >> 5;
    int lane = threadIdx.x & 31;
    if (w >= n) return;
    int beg = rs[w], end = rs[w + 1];
    float2 a = make_float2(0.f, 0.f);
    const float2* g2 = (const float2*)g;
    for (int j = beg; j < end; j++) {
        int s = __ldg(&csr[j]);
        float2 v = g2[(size_t)s * 32 + lane];
        a.x += v.x; a.y += v.y;
    }
    float dv = dinv[w];
    const float2* f2 = (const float2*)f;
    float2 fv = f2[(size_t)w * 32 + lane];
    float2 o;
    o.x = fv.x - a.x * dv;
    o.y = fv.y - a.y * dv;
    ((float2*)fout)[(size_t)w * 32 + lane] = o;
    if (gout) {
        float2 go; go.x = o.x * dv; go.y = o.y * dv;
        ((float2*)gout)[(size_t)w * 32 + lane] = go;
    }
}

// ---------------- combine: h_all[n,384] from the 6 filter states ----------------
__global__ void combine_k(const float4* __restrict__ a0, const float4* __restrict__ a1,
                          const float4* __restrict__ a2, const float4* __restrict__ b0,
                          const float4* __restrict__ b1, const float4* __restrict__ b2,
                          float4* __restrict__ out, int n) {
    int i = blockIdx.x * blockDim.x + threadIdx.x;
    if (i >= n * 16) return;
    int node = i >> 4, sub = i & 15;
    float4 v0 = a0[i], v1 = a1[i], v2 = a2[i];
    float4 u0 = b0[i], u1 = b1[i], u2 = b2[i];
    float4 r0, r1, r2, r3;
    r0.x = 3.f * v0.x - 3.f * v1.x + 0.75f * v2.x;
    r0.y = 3.f * v0.y - 3.f * v1.y + 0.75f * v2.y;
    r0.z = 3.f * v0.z - 3.f * v1.z + 0.75f * v2.z;
    r0.w = 3.f * v0.w - 3.f * v1.w + 0.75f * v2.w;
    r1.x = 3.f * v1.x - 1.5f * v2.x;
    r1.y = 3.f * v1.y - 1.5f * v2.y;
    r1.z = 3.f * v1.z - 1.5f * v2.z;
    r1.w = 3.f * v1.w - 1.5f * v2.w;
    r2.x = 0.75f * v2.x; r2.y = 0.75f * v2.y; r2.z = 0.75f * v2.z; r2.w = 0.75f * v2.w;
    r3.x = 4.f * (u0.x + u1.x + u2.x);
    r3.y = 4.f * (u0.y + u1.y + u2.y);
    r3.z = 4.f * (u0.z + u1.z + u2.z);
    r3.w = 4.f * (u0.w + u1.w + u2.w);
    float4* o = out + (size_t)node * 96;
    o[sub]      = r0;
    o[16 + sub] = r1;
    o[32 + sub] = r2;
    o[48 + sub] = r3;
    o[64 + sub] = r3;
    o[80 + sub] = r3;
}

// ---------------- fused 2-layer MLP head ----------------
// logits[n,2] = relu(h_all[n,384] @ Wm1[384,64] + bm1) @ Wm2[64,2] + bm2
__global__ void mlp_k(const float* __restrict__ hall, const float* __restrict__ Wm1,
                      const float* __restrict__ bm1, const float* __restrict__ Wm2,
                      const float* __restrict__ bm2, float* __restrict__ logits, int n) {
    __shared__ float Xs[16 * 384];  // 24 KB
    __shared__ float Wc[64 * 64];   // 16 KB
    __shared__ float Zs[16 * 64];   // 4 KB
    int tid = threadIdx.x;
    int col = tid & 63, grp = tid >> 6;
    int nb = blockIdx.x * 16;
    long lim = ((long)n - nb) * 384;
    if (lim > 16 * 384) lim = 16 * 384;
    for (int i = tid; i < 16 * 384; i += 256)
        Xs[i] = (i < lim) ? hall[(size_t)nb * 384 + i] : 0.f;
    float acc[4] = {0, 0, 0, 0};
    for (int kc = 0; kc < 6; kc++) {
        __syncthreads();
        for (int i = tid; i < 64 * 64; i += 256)
            Wc[i] = Wm1[(size_t)(kc * 64 + (i >> 6)) * 64 + (i & 63)];
        __syncthreads();
        #pragma unroll 8
        for (int k = 0; k < 64; k++) {
            float w = Wc[k * 64 + col];
            #pragma unroll
            for (int j = 0; j < 4; j++)
                acc[j] += Xs[(grp * 4 + j) * 384 + kc * 64 + k] * w;
        }
    }
    __syncthreads();
    float bb = bm1[col];
    #pragma unroll
    for (int j = 0; j < 4; j++) {
        float z = acc[j] + bb;
        Zs[(grp * 4 + j) * 64 + col] = z > 0.f ? z : 0.f;
    }
    __syncthreads();
    if (tid < 32) {
        int node = tid >> 1, jj = tid & 1;
        if (nb + node < n) {
            float s = bm2[jj];
            for (int c = 0; c < 64; c++) s += Zs[node * 64 + c] * Wm2[c * 2 + jj];
            logits[(size_t)(nb + node) * 2 + jj] = s;
        }
    }
}

// ---------------- launch ----------------
extern "C" void kernel_launch(void* const* d_in, const int* in_sizes, int n_in,
                              void* d_out, int out_size) {
    const float* x     = (const float*)d_in[0];
    const float* sim_x = (const float*)d_in[1];
    const int*   src   = (const int*)d_in[2];
    const int*   dst   = (const int*)d_in[3];
    const int*   ssrc  = (const int*)d_in[4];
    const int*   sdst  = (const int*)d_in[5];
    const float* W1o   = (const float*)d_in[6];
    const float* b1o   = (const float*)d_in[7];
    const float* W1s   = (const float*)d_in[8];
    const float* b1s   = (const float*)d_in[9];
    const float* Wm1   = (const float*)d_in[10];
    const float* bm1   = (const float*)d_in[11];
    const float* Wm2   = (const float*)d_in[12];
    const float* bm2   = (const float*)d_in[13];

    const int n = NN, ne = NE;

    float *fbuf; float *dinv; int *cnt, *cur, *rs, *csr;
    cudaGetSymbolAddress((void**)&fbuf, d_fbuf);
    cudaGetSymbolAddress((void**)&dinv, d_dinv);
    cudaGetSymbolAddress((void**)&cnt,  d_cnt);
    cudaGetSymbolAddress((void**)&cur,  d_cur);
    cudaGetSymbolAddress((void**)&rs,   d_rs);
    cudaGetSymbolAddress((void**)&csr,  d_csr);

    float* fo0 = fbuf + (size_t)0 * NN * HID;
    float* fo1 = fbuf + (size_t)1 * NN * HID;
    float* fo2 = fbuf + (size_t)2 * NN * HID;
    float* fs0 = fbuf + (size_t)3 * NN * HID;
    float* fs1 = fbuf + (size_t)4 * NN * HID;
    float* fs2 = fbuf + (size_t)5 * NN * HID;
    float* ga  = fbuf + (size_t)6 * NN * HID;
    float* gb  = fbuf + (size_t)7 * NN * HID;
    float* dinv_o = dinv;
    float* dinv_s = dinv + NN;
    int* cnt_o = cnt;       int* cnt_s = cnt + NN;
    int* cur_o = cur;       int* cur_s = cur + NN;
    int* rs_o  = rs;        int* rs_s  = rs + (NN + 1);
    int* csr_o = csr;       int* csr_s = csr + NE;

    cudaMemsetAsync(cnt, 0, (size_t)2 * NN * sizeof(int), 0);
    cudaMemsetAsync(cur, 0, (size_t)2 * NN * sizeof(int), 0);

    int eb = (ne + 255) / 256;
    count_k<<<eb, 256>>>(dst,  cnt_o, ne);
    count_k<<<eb, 256>>>(sdst, cnt_s, ne);
    scan_k<<<2, 1024>>>(cnt_o, rs_o, dinv_o, cnt_s, rs_s, dinv_s, n);
    fill_k<<<eb, 256>>>(src,  dst,  rs_o, cur_o, csr_o, ne);
    fill_k<<<eb, 256>>>(ssrc, sdst, rs_s, cur_s, csr_s, ne);

    int gb_gemm = (n + 31) / 32;
    gemm_relu_k<<<gb_gemm, 256>>>(x,     W1o, b1o, fo0, n);
    gemm_relu_k<<<gb_gemm, 256>>>(sim_x, W1s, b1s, fs0, n);

    int sb = (n * 16 + 255) / 256;
    int pb = (n * 32 + 255) / 256;

    // branch "o": f1 = M(f0), f2 = M(f1)
    scale_k<<<sb, 256>>>((const float4*)fo0, dinv_o, (float4*)ga, n);
    prop_k<<<pb, 256>>>(ga, fo0, dinv_o, rs_o, csr_o, fo1, gb, n);
    prop_k<<<pb, 256>>>(gb, fo1, dinv_o, rs_o, csr_o, fo2, nullptr, n);

    // branch "sim"
    scale_k<<<sb, 256>>>((const float4*)fs0, dinv_s, (float4*)ga, n);
    prop_k<<<pb, 256>>>(ga, fs0, dinv_s, rs_s, csr_s, fs1, gb, n);
    prop_k<<<pb, 256>>>(gb, fs1, dinv_s, rs_s, csr_s, fs2, nullptr, n);

    float* out    = (float*)d_out;
    float* logits = out + (size_t)n * 384;
    combine_k<<<sb, 256>>>((const float4*)fo0, (const float4*)fo1, (const float4*)fo2,
                           (const float4*)fs0, (const float4*)fs1, (const float4*)fs2,
                           (float4*)out, n);
    mlp_k<<<(n + 15) / 16, 256>>>(out, Wm1, bm1, Wm2, bm2, logits, n);
}

// round 3
// speedup vs baseline: 1.1365x; 1.1365x over previous
#include <cuda_runtime.h>
#include <cuda_bf16.h>
#include <stdint.h>

#define NN 50000
#define NE 800000
#define INF 128
#define HID 64
#define S ((size_t)NN * HID)

// ---------------- scratch (static device memory; no allocations) ----------------
// fbuf slots (each S floats): 0=fo0 1=fs0 2=fo1 3=fs1 4=fo2 5=fs2 6=ga_o 7=ga_s 8=gb_o 9=gb_s
__device__ float d_fbuf[(size_t)10 * NN * HID];
__device__ float d_dinv[2 * NN];
__device__ int   d_cnt [2 * NN];
__device__ int   d_cur [2 * NN];
__device__ int   d_rs  [2 * (NN + 1)];
__device__ int   d_csr [2 * NE];
__device__ float d_weff[4 * 64 * 64];

// ---------------- degree histogram (both branches, one launch) ----------------
__global__ void count_k(const int* __restrict__ d0, const int* __restrict__ d1,
                        int* __restrict__ cnt, int ne) {
    int i = blockIdx.x * blockDim.x + threadIdx.x;
    if (i >= 2 * ne) return;
    int b = (i >= ne) ? 1 : 0;
    int j = i - b * ne;
    int d = b ? d1[j] : d0[j];
    atomicAdd(&cnt[b * NN + d], 1);
}

// ---------------- exclusive scan + dinv (one block per branch) ----------------
__global__ void scan_k(const int* __restrict__ cnt0, int* __restrict__ rs0, float* __restrict__ dv0,
                       const int* __restrict__ cnt1, int* __restrict__ rs1, float* __restrict__ dv1,
                       int n) {
    const int* cnt = blockIdx.x ? cnt1 : cnt0;
    int*       rs  = blockIdx.x ? rs1  : rs0;
    float*     dv  = blockIdx.x ? dv1  : dv0;
    __shared__ int wsum[32];
    __shared__ int carry_s;
    int tid = threadIdx.x, lane = tid & 31, wid = tid >> 5;
    if (tid == 0) carry_s = 0;
    __syncthreads();
    for (int base = 0; base < n; base += 1024) {
        int i = base + tid;
        int v = (i < n) ? cnt[i] : 0;
        int x = v;
        #pragma unroll
        for (int d = 1; d < 32; d <<= 1) {
            int t = __shfl_up_sync(0xffffffffu, x, d);
            if (lane >= d) x += t;
        }
        if (lane == 31) wsum[wid] = x;
        __syncthreads();
        if (wid == 0) {
            int w = wsum[lane];
            int y = w;
            #pragma unroll
            for (int d = 1; d < 32; d <<= 1) {
                int t = __shfl_up_sync(0xffffffffu, y, d);
                if (lane >= d) y += t;
            }
            wsum[lane] = y - w;
        }
        __syncthreads();
        int excl = x - v + wsum[wid] + carry_s;
        if (i < n) {
            rs[i] = excl;
            dv[i] = rsqrtf((float)(v > 0 ? v : 1));
        }
        __syncthreads();
        if (tid == 1023) carry_s = excl + v;
        __syncthreads();
    }
    if (threadIdx.x == 0) rs[n] = carry_s;
}

// ---------------- CSR fill (both branches, one launch) ----------------
__global__ void fill_k(const int* __restrict__ s0, const int* __restrict__ s1,
                       const int* __restrict__ d0, const int* __restrict__ d1,
                       const int* __restrict__ rs, int* __restrict__ cur,
                       int* __restrict__ csr, int ne) {
    int i = blockIdx.x * blockDim.x + threadIdx.x;
    if (i >= 2 * ne) return;
    int b = (i >= ne) ? 1 : 0;
    int j = i - b * ne;
    int d  = b ? d1[j] : d0[j];
    int sv = b ? s1[j] : s0[j];
    const int* rsb = rs + b * (NN + 1);
    int p = rsb[d] + atomicAdd(&cur[b * NN + d], 1);
    csr[(size_t)b * NE + p] = sv;
}

// ---------------- effective first-layer weights ----------------
// h_all @ Wm1 = f0@(3W0) + f1@(-3W0+3W1) + f2@(0.75W0-1.5W1+0.75W2) + ssum@(4(W3+W4+W5))
__global__ void weff_k(const float* __restrict__ Wm1, float* __restrict__ weff) {
    int i = blockIdx.x * blockDim.x + threadIdx.x;
    if (i >= 4096) return;
    int r = i >> 6, c = i & 63;
    float w0 = Wm1[r * 64 + c];
    float w1 = Wm1[(64 + r) * 64 + c];
    float w2 = Wm1[(128 + r) * 64 + c];
    float w3 = Wm1[(192 + r) * 64 + c] + Wm1[(256 + r) * 64 + c] + Wm1[(320 + r) * 64 + c];
    weff[0 * 4096 + i] = 3.f * w0;
    weff[1 * 4096 + i] = -3.f * w0 + 3.f * w1;
    weff[2 * 4096 + i] = 0.75f * w0 - 1.5f * w1 + 0.75f * w2;
    weff[3 * 4096 + i] = 4.f * w3;
}

// ---------------- input GEMM + relu + dinv-scale (both branches via blockIdx.y) ----------------
__global__ void gemm_relu_k(const float* __restrict__ X0, const float* __restrict__ X1,
                            const float* __restrict__ W0, const float* __restrict__ W1,
                            const float* __restrict__ b0, const float* __restrict__ b1,
                            const float* __restrict__ dinv_all,
                            float* __restrict__ f0base, float* __restrict__ gbase, int n) {
    int by = blockIdx.y;
    const float* X = by ? X1 : X0;
    const float* W = by ? W1 : W0;
    const float* b = by ? b1 : b0;
    const float* dv = dinv_all + by * NN;
    float* H = f0base + (size_t)by * S;
    float* G = gbase  + (size_t)by * S;

    __shared__ float Ws[INF * HID];
    __shared__ float Xs[32 * INF];
    int tid = threadIdx.x;
    int col = tid & 63, grp = tid >> 6;
    int nb = blockIdx.x * 32;
    for (int i = tid; i < INF * HID; i += 256) Ws[i] = W[i];
    int lim = (n - nb) * INF;
    if (lim > 32 * INF) lim = 32 * INF;
    for (int i = tid; i < 32 * INF; i += 256)
        Xs[i] = (i < lim) ? X[(size_t)nb * INF + i] : 0.f;
    __syncthreads();
    float acc[8] = {0, 0, 0, 0, 0, 0, 0, 0};
    #pragma unroll 8
    for (int k = 0; k < INF; k++) {
        float w = Ws[k * HID + col];
        #pragma unroll
        for (int j = 0; j < 8; j++) acc[j] += Xs[(grp * 8 + j) * INF + k] * w;
    }
    float bb = b[col];
    #pragma unroll
    for (int j = 0; j < 8; j++) {
        int node = nb + grp * 8 + j;
        if (node < n) {
            float v = acc[j] + bb;
            v = v > 0.f ? v : 0.f;
            H[(size_t)node * HID + col] = v;
            G[(size_t)node * HID + col] = v * dv[node];
        }
    }
}

// ---------------- propagation step, both branches in one launch ----------------
// fout = f - dinv * sum_{src in N(v)} g[src];  optionally gout = fout * dinv
__global__ void prop_k(const float* __restrict__ gin, const float* __restrict__ fin,
                       float* __restrict__ fout, float* __restrict__ gout,
                       const float* __restrict__ dinv_all, const int* __restrict__ rs_all,
                       const int* __restrict__ csr_all, int n, int writeG) {
    int gw = (blockIdx.x * blockDim.x + threadIdx.x) >> 5;
    int lane = threadIdx.x & 31;
    if (gw >= 2 * n) return;
    int b = (gw >= n) ? 1 : 0;
    int w = gw - b * n;
    const float2* g2  = (const float2*)(gin + (size_t)b * S);
    const int*    rs  = rs_all + b * (NN + 1);
    const int*    csr = csr_all + (size_t)b * NE;
    int beg = rs[w], end = rs[w + 1];
    float2 a = make_float2(0.f, 0.f);
    for (int base = beg; base < end; base += 32) {
        int idx = base + lane;
        int sreg = (idx < end) ? csr[idx] : 0;
        int cnt = end - base;
        if (cnt > 32) cnt = 32;
        #pragma unroll 4
        for (int t = 0; t < cnt; t++) {
            int ss = __shfl_sync(0xffffffffu, sreg, t);
            float2 v = g2[(size_t)ss * 32 + lane];
            a.x += v.x; a.y += v.y;
        }
    }
    float dvv = dinv_all[b * NN + w];
    const float2* f2 = (const float2*)(fin + (size_t)b * S);
    float2 fv = f2[(size_t)w * 32 + lane];
    float2 o;
    o.x = fv.x - a.x * dvv;
    o.y = fv.y - a.y * dvv;
    ((float2*)(fout + (size_t)b * S))[(size_t)w * 32 + lane] = o;
    if (writeG) {
        float2 go;
        go.x = o.x * dvv; go.y = o.y * dvv;
        ((float2*)(gout + (size_t)b * S))[(size_t)w * 32 + lane] = go;
    }
}

// ---------------- fused tail: combine -> write h_all, then 2-layer MLP head ----------------
__global__ void tail_k(const float* __restrict__ fbuf, const float* __restrict__ weff,
                       const float* __restrict__ bm1, const float* __restrict__ Wm2,
                       const float* __restrict__ bm2,
                       float* __restrict__ out, float* __restrict__ logits, int n) {
    __shared__ float Xs[4][16 * 64];   // f0, f1, f2, ssum tiles  (16 KB)
    __shared__ float Wc[64 * 64];      // weff chunk              (16 KB)
    __shared__ float Zs[16 * 64];      // layer-1 activations     ( 4 KB)
    int tid = threadIdx.x;
    int col = tid & 63, grp = tid >> 6;
    int nb = blockIdx.x * 16;

    const float* fo0 = fbuf + 0 * S;
    const float* fs0 = fbuf + 1 * S;
    const float* fo1 = fbuf + 2 * S;
    const float* fs1 = fbuf + 3 * S;
    const float* fo2 = fbuf + 4 * S;
    const float* fs2 = fbuf + 5 * S;

    int lim64 = (n - nb) * 64;
    if (lim64 > 16 * 64) lim64 = 16 * 64;
    for (int i = tid; i < 16 * 64; i += 256) {
        size_t off = (size_t)nb * 64 + i;
        bool ok = i < lim64;
        Xs[0][i] = ok ? fo0[off] : 0.f;
        Xs[1][i] = ok ? fo1[off] : 0.f;
        Xs[2][i] = ok ? fo2[off] : 0.f;
        Xs[3][i] = ok ? (fs0[off] + fs1[off] + fs2[off]) : 0.f;
    }
    __syncthreads();

    // write h_all (16 x 384 per block)
    int lim384 = (n - nb) * 384;
    if (lim384 > 6144) lim384 = 6144;
    for (int i = tid; i < lim384; i += 256) {
        int node_l = i / 384;
        int c = i - node_l * 384;
        int seg = c >> 6, cc = c & 63;
        int xi = node_l * 64 + cc;
        float v;
        if (seg == 0) {
            v = 3.f * Xs[0][xi] - 3.f * Xs[1][xi] + 0.75f * Xs[2][xi];
        } else if (seg == 1) {
            v = 3.f * Xs[1][xi] - 1.5f * Xs[2][xi];
        } else if (seg == 2) {
            v = 0.75f * Xs[2][xi];
        } else {
            v = 4.f * Xs[3][xi];
        }
        out[(size_t)nb * 384 + i] = v;
    }

    // layer 1: 256-dim effective GEMM
    float acc[4] = {0, 0, 0, 0};
    for (int kc = 0; kc < 4; kc++) {
        __syncthreads();
        for (int i = tid; i < 4096; i += 256) Wc[i] = weff[kc * 4096 + i];
        __syncthreads();
        #pragma unroll 8
        for (int k = 0; k < 64; k++) {
            float w = Wc[k * 64 + col];
            #pragma unroll
            for (int j = 0; j < 4; j++)
                acc[j] += Xs[kc][(grp * 4 + j) * 64 + k] * w;
        }
    }
    __syncthreads();
    float bb = bm1[col];
    #pragma unroll
    for (int j = 0; j < 4; j++) {
        float z = acc[j] + bb;
        Zs[(grp * 4 + j) * 64 + col] = z > 0.f ? z : 0.f;
    }
    __syncthreads();

    // layer 2
    if (tid < 32) {
        int node = tid >> 1, jj = tid & 1;
        if (nb + node < n) {
            float s = bm2[jj];
            #pragma unroll 8
            for (int c = 0; c < 64; c++) s += Zs[node * 64 + c] * Wm2[c * 2 + jj];
            logits[(size_t)(nb + node) * 2 + jj] = s;
        }
    }
}

// ---------------- launch ----------------
extern "C" void kernel_launch(void* const* d_in, const int* in_sizes, int n_in,
                              void* d_out, int out_size) {
    const float* x     = (const float*)d_in[0];
    const float* sim_x = (const float*)d_in[1];
    const int*   src   = (const int*)d_in[2];
    const int*   dst   = (const int*)d_in[3];
    const int*   ssrc  = (const int*)d_in[4];
    const int*   sdst  = (const int*)d_in[5];
    const float* W1o   = (const float*)d_in[6];
    const float* b1o   = (const float*)d_in[7];
    const float* W1s   = (const float*)d_in[8];
    const float* b1s   = (const float*)d_in[9];
    const float* Wm1   = (const float*)d_in[10];
    const float* bm1   = (const float*)d_in[11];
    const float* Wm2   = (const float*)d_in[12];
    const float* bm2   = (const float*)d_in[13];

    const int n = NN, ne = NE;

    float *fbuf, *dinv, *weff; int *cnt, *cur, *rs, *csr;
    cudaGetSymbolAddress((void**)&fbuf, d_fbuf);
    cudaGetSymbolAddress((void**)&dinv, d_dinv);
    cudaGetSymbolAddress((void**)&cnt,  d_cnt);
    cudaGetSymbolAddress((void**)&cur,  d_cur);
    cudaGetSymbolAddress((void**)&rs,   d_rs);
    cudaGetSymbolAddress((void**)&csr,  d_csr);
    cudaGetSymbolAddress((void**)&weff, d_weff);

    float* f0base = fbuf + 0 * S;   // fo0, fs0
    float* f1base = fbuf + 2 * S;   // fo1, fs1
    float* f2base = fbuf + 4 * S;   // fo2, fs2
    float* gabase = fbuf + 6 * S;   // ga_o, ga_s
    float* gbbase = fbuf + 8 * S;   // gb_o, gb_s

    cudaMemsetAsync(cnt, 0, (size_t)2 * NN * sizeof(int), 0);
    cudaMemsetAsync(cur, 0, (size_t)2 * NN * sizeof(int), 0);

    int eb2 = (2 * ne + 255) / 256;
    count_k<<<eb2, 256>>>(dst, sdst, cnt, ne);
    scan_k<<<2, 1024>>>(cnt, rs, dinv, cnt + NN, rs + (NN + 1), dinv + NN, n);
    fill_k<<<eb2, 256>>>(src, ssrc, dst, sdst, rs, cur, csr, ne);
    weff_k<<<16, 256>>>(Wm1, weff);

    dim3 gg((n + 31) / 32, 2);
    gemm_relu_k<<<gg, 256>>>(x, sim_x, W1o, W1s, b1o, b1s, dinv, f0base, gabase, n);

    int pb = (2 * n * 32 + 255) / 256;
    prop_k<<<pb, 256>>>(gabase, f0base, f1base, gbbase, dinv, rs, csr, n, 1);
    prop_k<<<pb, 256>>>(gbbase, f1base, f2base, nullptr, dinv, rs, csr, n, 0);

    float* out    = (float*)d_out;
    float* logits = out + (size_t)n * 384;
    tail_k<<<(n + 15) / 16, 256>>>(fbuf, weff, bm1, Wm2, bm2, out, logits, n);
}

// round 5
// speedup vs baseline: 1.2229x; 1.0760x over previous
#include <cuda_runtime.h>
#include <cuda_bf16.h>
#include <stdint.h>

#define NN 50000
#define NE 800000
#define INF 128
#define HID 64
#define S ((size_t)NN * HID)

// packed dual fp32 FMA (sm_103a): d = a*b + c elementwise on 2 packed floats
#define FMA_F32X2(d, a, b, c) \
    asm("fma.rn.f32x2 %0, %1, %2, %3;" : "=l"(d) : "l"(a), "l"(b), "l"(c))

__device__ __forceinline__ float x2lo(unsigned long long v) {
    return __uint_as_float((unsigned)(v & 0xffffffffull));
}
__device__ __forceinline__ float x2hi(unsigned long long v) {
    return __uint_as_float((unsigned)(v >> 32));
}

// ---------------- scratch ----------------
// fbuf slots (each S floats): 0=fo0 1=fs0 2=fo1 3=fs1 4=fo2 5=fs2 6=ga_o 7=ga_s 8=gb_o 9=gb_s
__device__ float d_fbuf[(size_t)10 * NN * HID];
__device__ float d_dinv[2 * NN];
__device__ int   d_cnt [2 * NN];
__device__ int   d_cur [2 * NN];
__device__ int   d_rs  [2 * (NN + 1)];
__device__ int   d_csr [2 * NE];
// interleaved weights: Wp1o[64kp][64c][2] (8192) | Wp1s (8192) | Weffp[128kp][64c][2] (16384)
__device__ float d_wp[32768];

// ---------------- degree histogram (both branches) ----------------
__global__ void count_k(const int* __restrict__ d0, const int* __restrict__ d1,
                        int* __restrict__ cnt, int ne) {
    int i = blockIdx.x * blockDim.x + threadIdx.x;
    if (i >= 2 * ne) return;
    int b = (i >= ne) ? 1 : 0;
    int j = i - b * ne;
    int d = b ? d1[j] : d0[j];
    atomicAdd(&cnt[b * NN + d], 1);
}

// ---------------- exclusive scan + dinv + cur init (one block per branch) ----------------
__global__ void scan_k(const int* __restrict__ cntA, int* __restrict__ rsA,
                       float* __restrict__ dvA, int* __restrict__ curA, int n) {
    const int* cnt = cntA + blockIdx.x * NN;
    int*       rs  = rsA  + blockIdx.x * (NN + 1);
    float*     dv  = dvA  + blockIdx.x * NN;
    int*       cur = curA + blockIdx.x * NN;
    __shared__ int wsum[32];
    __shared__ int carry_s;
    int tid = threadIdx.x, lane = tid & 31, wid = tid >> 5;
    if (tid == 0) carry_s = 0;
    __syncthreads();
    for (int base = 0; base < n; base += 1024) {
        int i = base + tid;
        int v = (i < n) ? cnt[i] : 0;
        int x = v;
        #pragma unroll
        for (int d = 1; d < 32; d <<= 1) {
            int t = __shfl_up_sync(0xffffffffu, x, d);
            if (lane >= d) x += t;
        }
        if (lane == 31) wsum[wid] = x;
        __syncthreads();
        if (wid == 0) {
            int w = wsum[lane];
            int y = w;
            #pragma unroll
            for (int d = 1; d < 32; d <<= 1) {
                int t = __shfl_up_sync(0xffffffffu, y, d);
                if (lane >= d) y += t;
            }
            wsum[lane] = y - w;
        }
        __syncthreads();
        int excl = x - v + wsum[wid] + carry_s;
        if (i < n) {
            rs[i]  = excl;
            cur[i] = excl;
            dv[i]  = rsqrtf((float)(v > 0 ? v : 1));
        }
        __syncthreads();
        if (tid == 1023) carry_s = excl + v;
        __syncthreads();
    }
    if (threadIdx.x == 0) rs[n] = carry_s;
}

// ---------------- CSR fill (cur preloaded with row starts) ----------------
__global__ void fill_k(const int* __restrict__ s0, const int* __restrict__ s1,
                       const int* __restrict__ d0, const int* __restrict__ d1,
                       int* __restrict__ cur, int* __restrict__ csr, int ne) {
    int i = blockIdx.x * blockDim.x + threadIdx.x;
    if (i >= 2 * ne) return;
    int b = (i >= ne) ? 1 : 0;
    int j = i - b * ne;
    int d  = b ? d1[j] : d0[j];
    int sv = b ? s1[j] : s0[j];
    int p = atomicAdd(&cur[b * NN + d], 1);
    csr[(size_t)b * NE + p] = sv;
}

// ---------------- weight interleave + combine-fold ----------------
// Wp1o / Wp1s: [kp][c][2] from W[2kp+j][c]
// Weffp: layer-1 effective weights in basis (f0, f1, f2, ssum), rows r=0..255:
//   r in [0,64):   3*W0_r
//   r in [64,128): -3*W0 + 3*W1
//   r in [128,192): 0.75*W0 - 1.5*W1 + 0.75*W2
//   r in [192,256): 4*(W3+W4+W5)
__global__ void prep_k(const float* __restrict__ W1o, const float* __restrict__ W1s,
                       const float* __restrict__ Wm1, float* __restrict__ wp) {
    int i = blockIdx.x * blockDim.x + threadIdx.x;
    if (i >= 32768) return;
    if (i < 16384) {
        int b = i >> 13;           // 0=o, 1=s
        int pos = i & 8191;
        int j = pos & 1, c = (pos >> 1) & 63, kp = pos >> 7;
        const float* W = b ? W1s : W1o;
        wp[i] = W[(2 * kp + j) * 64 + c];
    } else {
        int pos = i - 16384;
        int j = pos & 1, c = (pos >> 1) & 63, kp = pos >> 7;
        int r = 2 * kp + j;
        int s = r >> 6, kk = r & 63;
        float w0 = Wm1[kk * 64 + c];
        float w1 = Wm1[(64 + kk) * 64 + c];
        float w2 = Wm1[(128 + kk) * 64 + c];
        float v;
        if (s == 0)      v = 3.f * w0;
        else if (s == 1) v = -3.f * w0 + 3.f * w1;
        else if (s == 2) v = 0.75f * w0 - 1.5f * w1 + 0.75f * w2;
        else v = 4.f * (Wm1[(192 + kk) * 64 + c] + Wm1[(256 + kk) * 64 + c] +
                        Wm1[(320 + kk) * 64 + c]);
        wp[i] = v;
    }
}

// ---------------- input GEMM + relu + dinv-scale (FFMA2, k-paired) ----------------
// block: 32 nodes x 64 cols, 256 threads; thread: 4 nodes x cols (cp, cp+32)
__global__ void gemm_relu_k(const float* __restrict__ X0, const float* __restrict__ X1,
                            const float* __restrict__ wp,
                            const float* __restrict__ b0, const float* __restrict__ b1,
                            const float* __restrict__ dinv_all,
                            float* __restrict__ f0base, float* __restrict__ gbase, int n) {
    __shared__ float Xs[32 * 128];     // 16 KB, node-major
    __shared__ float Wpc[4096];        // 16 KB, [32kp][64c][2]
    int by = blockIdx.y;
    const float* X  = by ? X1 : X0;
    const float* Wp = wp + by * 8192;
    const float* b  = by ? b1 : b0;
    const float* dv = dinv_all + by * NN;
    float* H = f0base + (size_t)by * S;
    float* G = gbase  + (size_t)by * S;

    int tid = threadIdx.x;
    int cp = tid & 31, ng = tid >> 5;
    int nb = blockIdx.x * 32;

    int lim = (n - nb) * 128;
    if (lim > 32 * 128) lim = 32 * 128;
    for (int i = tid; i < 32 * 128; i += 256)
        Xs[i] = (i < lim) ? X[(size_t)nb * 128 + i] : 0.f;

    unsigned long long acc0[4] = {0, 0, 0, 0};  // col cp
    unsigned long long acc1[4] = {0, 0, 0, 0};  // col cp+32

    #pragma unroll
    for (int ch = 0; ch < 2; ch++) {
        __syncthreads();
        for (int i = tid; i < 4096; i += 256) Wpc[i] = Wp[ch * 4096 + i];
        __syncthreads();
        #pragma unroll 8
        for (int kp = 0; kp < 32; kp++) {
            unsigned long long w0 = *(const unsigned long long*)&Wpc[(kp * 64 + cp) * 2];
            unsigned long long w1 = *(const unsigned long long*)&Wpc[(kp * 64 + cp + 32) * 2];
            #pragma unroll
            for (int j = 0; j < 4; j++) {
                unsigned long long x =
                    *(const unsigned long long*)&Xs[(ng * 4 + j) * 128 + ch * 64 + 2 * kp];
                FMA_F32X2(acc0[j], x, w0, acc0[j]);
                FMA_F32X2(acc1[j], x, w1, acc1[j]);
            }
        }
    }

    float bb0 = b[cp], bb1 = b[cp + 32];
    #pragma unroll
    for (int j = 0; j < 4; j++) {
        int node = nb + ng * 4 + j;
        if (node < n) {
            float dvv = dv[node];
            float v0 = x2lo(acc0[j]) + x2hi(acc0[j]) + bb0;
            float v1 = x2lo(acc1[j]) + x2hi(acc1[j]) + bb1;
            v0 = v0 > 0.f ? v0 : 0.f;
            v1 = v1 > 0.f ? v1 : 0.f;
            size_t base = (size_t)node * 64;
            H[base + cp]      = v0;
            H[base + cp + 32] = v1;
            G[base + cp]      = v0 * dvv;
            G[base + cp + 32] = v1 * dvv;
        }
    }
}

// ---------------- propagation step, both branches ----------------
__global__ void prop_k(const float* __restrict__ gin, const float* __restrict__ fin,
                       float* __restrict__ fout, float* __restrict__ gout,
                       const float* __restrict__ dinv_all, const int* __restrict__ rs_all,
                       const int* __restrict__ csr_all, int n, int writeG) {
    int gw = (blockIdx.x * blockDim.x + threadIdx.x) >> 5;
    int lane = threadIdx.x & 31;
    if (gw >= 2 * n) return;
    int b = (gw >= n) ? 1 : 0;
    int w = gw - b * n;
    const float2* g2  = (const float2*)(gin + (size_t)b * S);
    const int*    rs  = rs_all + b * (NN + 1);
    const int*    csr = csr_all + (size_t)b * NE;
    int beg = rs[w], end = rs[w + 1];
    float2 a = make_float2(0.f, 0.f);
    int base = beg;
    for (; base + 32 <= end; base += 32) {
        int sreg = csr[base + lane];
        #pragma unroll
        for (int t = 0; t < 32; t++) {
            int ss = __shfl_sync(0xffffffffu, sreg, t);
            float2 v = g2[(size_t)ss * 32 + lane];
            a.x += v.x; a.y += v.y;
        }
    }
    int rem = end - base;
    if (rem > 0) {
        int sreg = (base + lane < end) ? csr[base + lane] : 0;
        for (int t = 0; t < rem; t++) {
            int ss = __shfl_sync(0xffffffffu, sreg, t);
            float2 v = g2[(size_t)ss * 32 + lane];
            a.x += v.x; a.y += v.y;
        }
    }
    float dvv = dinv_all[b * NN + w];
    const float2* f2 = (const float2*)(fin + (size_t)b * S);
    float2 fv = f2[(size_t)w * 32 + lane];
    float2 o;
    o.x = fv.x - a.x * dvv;
    o.y = fv.y - a.y * dvv;
    ((float2*)(fout + (size_t)b * S))[(size_t)w * 32 + lane] = o;
    if (writeG) {
        float2 go;
        go.x = o.x * dvv; go.y = o.y * dvv;
        ((float2*)(gout + (size_t)b * S))[(size_t)w * 32 + lane] = go;
    }
}

// ---------------- fused tail: combine -> h_all, then 2-layer MLP (FFMA2) ----------------
// block: 16 nodes; 256 threads; thread: 2 nodes x cols (cp, cp+32)
__global__ void tail_k(const float* __restrict__ fbuf, const float* __restrict__ wp,
                       const float* __restrict__ bm1, const float* __restrict__ Wm2,
                       const float* __restrict__ bm2,
                       float* __restrict__ out, float* __restrict__ logits, int n) {
    __shared__ float Xs[4][16 * 64];   // f0, f1, f2, ssum (16 KB)
    __shared__ float Wpc[4096];        // 16 KB
    __shared__ float Zs[16 * 64];      // 4 KB
    int tid = threadIdx.x;
    int cp = tid & 31, ng = tid >> 5;
    int nb = blockIdx.x * 16;
    const float* weffp = wp + 16384;

    const float* fo0 = fbuf + 0 * S;
    const float* fs0 = fbuf + 1 * S;
    const float* fo1 = fbuf + 2 * S;
    const float* fs1 = fbuf + 3 * S;
    const float* fo2 = fbuf + 4 * S;
    const float* fs2 = fbuf + 5 * S;

    int lim64 = (n - nb) * 64;
    if (lim64 > 16 * 64) lim64 = 16 * 64;
    for (int i = tid; i < 16 * 64; i += 256) {
        size_t off = (size_t)nb * 64 + i;
        bool ok = i < lim64;
        Xs[0][i] = ok ? fo0[off] : 0.f;
        Xs[1][i] = ok ? fo1[off] : 0.f;
        Xs[2][i] = ok ? fo2[off] : 0.f;
        Xs[3][i] = ok ? (fs0[off] + fs1[off] + fs2[off]) : 0.f;
    }
    __syncthreads();

    // h_all
    int lim384 = (n - nb) * 384;
    if (lim384 > 6144) lim384 = 6144;
    for (int i = tid; i < lim384; i += 256) {
        int node_l = i / 384;
        int c = i - node_l * 384;
        int seg = c >> 6, cc = c & 63;
        int xi = node_l * 64 + cc;
        float v;
        if (seg == 0)      v = 3.f * Xs[0][xi] - 3.f * Xs[1][xi] + 0.75f * Xs[2][xi];
        else if (seg == 1) v = 3.f * Xs[1][xi] - 1.5f * Xs[2][xi];
        else if (seg == 2) v = 0.75f * Xs[2][xi];
        else               v = 4.f * Xs[3][xi];
        out[(size_t)nb * 384 + i] = v;
    }

    // layer 1 (K = 4 x 64)
    unsigned long long acc0[2] = {0, 0};
    unsigned long long acc1[2] = {0, 0};
    #pragma unroll
    for (int s = 0; s < 4; s++) {
        __syncthreads();
        for (int i = tid; i < 4096; i += 256) Wpc[i] = weffp[s * 4096 + i];
        __syncthreads();
        #pragma unroll 8
        for (int kp = 0; kp < 32; kp++) {
            unsigned long long w0 = *(const unsigned long long*)&Wpc[(kp * 64 + cp) * 2];
            unsigned long long w1 = *(const unsigned long long*)&Wpc[(kp * 64 + cp + 32) * 2];
            #pragma unroll
            for (int j = 0; j < 2; j++) {
                unsigned long long x =
                    *(const unsigned long long*)&Xs[s][(ng * 2 + j) * 64 + 2 * kp];
                FMA_F32X2(acc0[j], x, w0, acc0[j]);
                FMA_F32X2(acc1[j], x, w1, acc1[j]);
            }
        }
    }
    __syncthreads();
    float bb0 = bm1[cp], bb1 = bm1[cp + 32];
    #pragma unroll
    for (int j = 0; j < 2; j++) {
        float z0 = x2lo(acc0[j]) + x2hi(acc0[j]) + bb0;
        float z1 = x2lo(acc1[j]) + x2hi(acc1[j]) + bb1;
        Zs[(ng * 2 + j) * 64 + cp]      = z0 > 0.f ? z0 : 0.f;
        Zs[(ng * 2 + j) * 64 + cp + 32] = z1 > 0.f ? z1 : 0.f;
    }
    __syncthreads();

    // layer 2
    if (tid < 32) {
        int node = tid >> 1, jj = tid & 1;
        if (nb + node < n) {
            float sacc = bm2[jj];
            #pragma unroll 8
            for (int c = 0; c < 64; c++) sacc += Zs[node * 64 + c] * Wm2[c * 2 + jj];
            logits[(size_t)(nb + node) * 2 + jj] = sacc;
        }
    }
}

// ---------------- launch ----------------
extern "C" void kernel_launch(void* const* d_in, const int* in_sizes, int n_in,
                              void* d_out, int out_size) {
    const float* x     = (const float*)d_in[0];
    const float* sim_x = (const float*)d_in[1];
    const int*   src   = (const int*)d_in[2];
    const int*   dst   = (const int*)d_in[3];
    const int*   ssrc  = (const int*)d_in[4];
    const int*   sdst  = (const int*)d_in[5];
    const float* W1o   = (const float*)d_in[6];
    const float* b1o   = (const float*)d_in[7];
    const float* W1s   = (const float*)d_in[8];
    const float* b1s   = (const float*)d_in[9];
    const float* Wm1   = (const float*)d_in[10];
    const float* bm1   = (const float*)d_in[11];
    const float* Wm2   = (const float*)d_in[12];
    const float* bm2   = (const float*)d_in[13];

    const int n = NN, ne = NE;

    float *fbuf, *dinv, *wp; int *cnt, *cur, *rs, *csr;
    cudaGetSymbolAddress((void**)&fbuf, d_fbuf);
    cudaGetSymbolAddress((void**)&dinv, d_dinv);
    cudaGetSymbolAddress((void**)&cnt,  d_cnt);
    cudaGetSymbolAddress((void**)&cur,  d_cur);
    cudaGetSymbolAddress((void**)&rs,   d_rs);
    cudaGetSymbolAddress((void**)&csr,  d_csr);
    cudaGetSymbolAddress((void**)&wp,   d_wp);

    float* f0base = fbuf + 0 * S;
    float* f1base = fbuf + 2 * S;
    float* f2base = fbuf + 4 * S;
    float* gabase = fbuf + 6 * S;
    float* gbbase = fbuf + 8 * S;

    cudaMemsetAsync(cnt, 0, (size_t)2 * NN * sizeof(int), 0);

    int eb2 = (2 * ne + 255) / 256;
    count_k<<<eb2, 256>>>(dst, sdst, cnt, ne);
    scan_k<<<2, 1024>>>(cnt, rs, dinv, cur, n);
    fill_k<<<eb2, 256>>>(src, ssrc, dst, sdst, cur, csr, ne);
    prep_k<<<128, 256>>>(W1o, W1s, Wm1, wp);

    dim3 gg((n + 31) / 32, 2);
    gemm_relu_k<<<gg, 256>>>(x, sim_x, wp, b1o, b1s, dinv, f0base, gabase, n);

    int pb = (2 * n * 32 + 255) / 256;
    prop_k<<<pb, 256>>>(gabase, f0base, f1base, gbbase, dinv, rs, csr, n, 1);
    prop_k<<<pb, 256>>>(gbbase, f1base, f2base, nullptr, dinv, rs, csr, n, 0);

    float* out    = (float*)d_out;
    float* logits = out + (size_t)n * 384;
    tail_k<<<(n + 15) / 16, 256>>>(fbuf, wp, bm1, Wm2, bm2, out, logits, n);
}

// round 6
// speedup vs baseline: 1.2897x; 1.0546x over previous
#include <cuda_runtime.h>
#include <cuda_bf16.h>
#include <cuda_fp16.h>
#include <stdint.h>

#define NN 50000
#define NE 800000
#define INF 128
#define HID 64
#define S ((size_t)NN * HID)

// packed dual fp32 FMA (sm_103a)
#define FMA_F32X2(d, a, b, c) \
    asm("fma.rn.f32x2 %0, %1, %2, %3;" : "=l"(d) : "l"(a), "l"(b), "l"(c))

__device__ __forceinline__ float x2lo(unsigned long long v) {
    return __uint_as_float((unsigned)(v & 0xffffffffull));
}
__device__ __forceinline__ float x2hi(unsigned long long v) {
    return __uint_as_float((unsigned)(v >> 32));
}

// ---------------- scratch ----------------
// fbuf slots (each S floats): 0=fo0 1=fs0 2=fo1 3=fs1 4=fo2 5=fs2
__device__ float d_fbuf[(size_t)6 * NN * HID];
// fp16 scaled buffers: ga (2 branches) then gb (2 branches)
__device__ __align__(16) __half d_gh[(size_t)4 * NN * HID];
__device__ float d_dinv[2 * NN];
__device__ int   d_cnt [2 * NN];
__device__ int   d_cur [2 * NN];
__device__ int   d_rs  [2 * (NN + 1)];
__device__ int   d_csr [2 * NE];
// interleaved weights: Wp1o (8192) | Wp1s (8192) | Weffp (16384)
__device__ float d_wp[32768];

// ---------------- degree histogram (both branches) ----------------
__global__ void count_k(const int* __restrict__ d0, const int* __restrict__ d1,
                        int* __restrict__ cnt, int ne) {
    int i = blockIdx.x * blockDim.x + threadIdx.x;
    if (i >= 2 * ne) return;
    int b = (i >= ne) ? 1 : 0;
    int j = i - b * ne;
    int d = b ? d1[j] : d0[j];
    atomicAdd(&cnt[b * NN + d], 1);
}

// ---------------- exclusive scan + dinv + cur init (one block per branch) ----------------
__global__ void scan_k(const int* __restrict__ cntA, int* __restrict__ rsA,
                       float* __restrict__ dvA, int* __restrict__ curA, int n) {
    const int* cnt = cntA + blockIdx.x * NN;
    int*       rs  = rsA  + blockIdx.x * (NN + 1);
    float*     dv  = dvA  + blockIdx.x * NN;
    int*       cur = curA + blockIdx.x * NN;
    __shared__ int wsum[32];
    __shared__ int carry_s;
    int tid = threadIdx.x, lane = tid & 31, wid = tid >> 5;
    if (tid == 0) carry_s = 0;
    __syncthreads();
    for (int base = 0; base < n; base += 1024) {
        int i = base + tid;
        int v = (i < n) ? cnt[i] : 0;
        int x = v;
        #pragma unroll
        for (int d = 1; d < 32; d <<= 1) {
            int t = __shfl_up_sync(0xffffffffu, x, d);
            if (lane >= d) x += t;
        }
        if (lane == 31) wsum[wid] = x;
        __syncthreads();
        if (wid == 0) {
            int w = wsum[lane];
            int y = w;
            #pragma unroll
            for (int d = 1; d < 32; d <<= 1) {
                int t = __shfl_up_sync(0xffffffffu, y, d);
                if (lane >= d) y += t;
            }
            wsum[lane] = y - w;
        }
        __syncthreads();
        int excl = x - v + wsum[wid] + carry_s;
        if (i < n) {
            rs[i]  = excl;
            cur[i] = excl;
            dv[i]  = rsqrtf((float)(v > 0 ? v : 1));
        }
        __syncthreads();
        if (tid == 1023) carry_s = excl + v;
        __syncthreads();
    }
    if (threadIdx.x == 0) rs[n] = carry_s;
}

// ---------------- CSR fill (cur preloaded with row starts) ----------------
__global__ void fill_k(const int* __restrict__ s0, const int* __restrict__ s1,
                       const int* __restrict__ d0, const int* __restrict__ d1,
                       int* __restrict__ cur, int* __restrict__ csr, int ne) {
    int i = blockIdx.x * blockDim.x + threadIdx.x;
    if (i >= 2 * ne) return;
    int b = (i >= ne) ? 1 : 0;
    int j = i - b * ne;
    int d  = b ? d1[j] : d0[j];
    int sv = b ? s1[j] : s0[j];
    int p = atomicAdd(&cur[b * NN + d], 1);
    csr[(size_t)b * NE + p] = sv;
}

// ---------------- weight interleave + combine-fold ----------------
__global__ void prep_k(const float* __restrict__ W1o, const float* __restrict__ W1s,
                       const float* __restrict__ Wm1, float* __restrict__ wp) {
    int i = blockIdx.x * blockDim.x + threadIdx.x;
    if (i >= 32768) return;
    if (i < 16384) {
        int b = i >> 13;
        int pos = i & 8191;
        int j = pos & 1, c = (pos >> 1) & 63, kp = pos >> 7;
        const float* W = b ? W1s : W1o;
        wp[i] = W[(2 * kp + j) * 64 + c];
    } else {
        int pos = i - 16384;
        int j = pos & 1, c = (pos >> 1) & 63, kp = pos >> 7;
        int r = 2 * kp + j;
        int s = r >> 6, kk = r & 63;
        float w0 = Wm1[kk * 64 + c];
        float w1 = Wm1[(64 + kk) * 64 + c];
        float w2 = Wm1[(128 + kk) * 64 + c];
        float v;
        if (s == 0)      v = 3.f * w0;
        else if (s == 1) v = -3.f * w0 + 3.f * w1;
        else if (s == 2) v = 0.75f * w0 - 1.5f * w1 + 0.75f * w2;
        else v = 4.f * (Wm1[(192 + kk) * 64 + c] + Wm1[(256 + kk) * 64 + c] +
                        Wm1[(320 + kk) * 64 + c]);
        wp[i] = v;
    }
}

// ---------------- input GEMM + relu + fp16 dinv-scale ----------------
__global__ void gemm_relu_k(const float* __restrict__ X0, const float* __restrict__ X1,
                            const float* __restrict__ wp,
                            const float* __restrict__ b0, const float* __restrict__ b1,
                            const float* __restrict__ dinv_all,
                            float* __restrict__ f0base, __half* __restrict__ gbase, int n) {
    __shared__ float Xs[32 * 128];
    __shared__ float Wpc[4096];
    int by = blockIdx.y;
    const float* X  = by ? X1 : X0;
    const float* Wp = wp + by * 8192;
    const float* b  = by ? b1 : b0;
    const float* dv = dinv_all + by * NN;
    float*  H = f0base + (size_t)by * S;
    __half* G = gbase  + (size_t)by * S;

    int tid = threadIdx.x;
    int cp = tid & 31, ng = tid >> 5;
    int nb = blockIdx.x * 32;

    int lim = (n - nb) * 128;
    if (lim > 32 * 128) lim = 32 * 128;
    for (int i = tid; i < 32 * 128; i += 256)
        Xs[i] = (i < lim) ? X[(size_t)nb * 128 + i] : 0.f;

    unsigned long long acc0[4] = {0, 0, 0, 0};
    unsigned long long acc1[4] = {0, 0, 0, 0};

    #pragma unroll
    for (int ch = 0; ch < 2; ch++) {
        __syncthreads();
        for (int i = tid; i < 4096; i += 256) Wpc[i] = Wp[ch * 4096 + i];
        __syncthreads();
        #pragma unroll 8
        for (int kp = 0; kp < 32; kp++) {
            unsigned long long w0 = *(const unsigned long long*)&Wpc[(kp * 64 + cp) * 2];
            unsigned long long w1 = *(const unsigned long long*)&Wpc[(kp * 64 + cp + 32) * 2];
            #pragma unroll
            for (int j = 0; j < 4; j++) {
                unsigned long long x =
                    *(const unsigned long long*)&Xs[(ng * 4 + j) * 128 + ch * 64 + 2 * kp];
                FMA_F32X2(acc0[j], x, w0, acc0[j]);
                FMA_F32X2(acc1[j], x, w1, acc1[j]);
            }
        }
    }

    float bb0 = b[cp], bb1 = b[cp + 32];
    #pragma unroll
    for (int j = 0; j < 4; j++) {
        int node = nb + ng * 4 + j;
        if (node < n) {
            float dvv = dv[node];
            float v0 = x2lo(acc0[j]) + x2hi(acc0[j]) + bb0;
            float v1 = x2lo(acc1[j]) + x2hi(acc1[j]) + bb1;
            v0 = v0 > 0.f ? v0 : 0.f;
            v1 = v1 > 0.f ? v1 : 0.f;
            size_t base = (size_t)node * 64;
            H[base + cp]      = v0;
            H[base + cp + 32] = v1;
            G[base + cp]      = __float2half_rn(v0 * dvv);
            G[base + cp + 32] = __float2half_rn(v1 * dvv);
        }
    }
}

// ---------------- propagation step (fp16 gather), both branches ----------------
__global__ void prop_k(const __half* __restrict__ gin, const float* __restrict__ fin,
                       float* __restrict__ fout, __half* __restrict__ gout,
                       const float* __restrict__ dinv_all, const int* __restrict__ rs_all,
                       const int* __restrict__ csr_all, int n, int writeG) {
    int gw = (blockIdx.x * blockDim.x + threadIdx.x) >> 5;
    int lane = threadIdx.x & 31;
    if (gw >= 2 * n) return;
    int b = (gw >= n) ? 1 : 0;
    int w = gw - b * n;
    const __half2* g2  = (const __half2*)(gin + (size_t)b * S);
    const int*     rs  = rs_all + b * (NN + 1);
    const int*     csr = csr_all + (size_t)b * NE;
    int beg = rs[w], end = rs[w + 1];
    float2 a = make_float2(0.f, 0.f);
    int base = beg;
    for (; base + 32 <= end; base += 32) {
        int sreg = csr[base + lane];
        #pragma unroll
        for (int t = 0; t < 32; t++) {
            int ss = __shfl_sync(0xffffffffu, sreg, t);
            float2 v = __half22float2(g2[(size_t)ss * 32 + lane]);
            a.x += v.x; a.y += v.y;
        }
    }
    int rem = end - base;
    if (rem > 0) {
        int sreg = (base + lane < end) ? csr[base + lane] : 0;
        for (int t = 0; t < rem; t++) {
            int ss = __shfl_sync(0xffffffffu, sreg, t);
            float2 v = __half22float2(g2[(size_t)ss * 32 + lane]);
            a.x += v.x; a.y += v.y;
        }
    }
    float dvv = dinv_all[b * NN + w];
    const float2* f2 = (const float2*)(fin + (size_t)b * S);
    float2 fv = f2[(size_t)w * 32 + lane];
    float2 o;
    o.x = fv.x - a.x * dvv;
    o.y = fv.y - a.y * dvv;
    ((float2*)(fout + (size_t)b * S))[(size_t)w * 32 + lane] = o;
    if (writeG) {
        float2 go;
        go.x = o.x * dvv; go.y = o.y * dvv;
        ((__half2*)(gout + (size_t)b * S))[(size_t)w * 32 + lane] = __float22half2_rn(go);
    }
}

// ---------------- fused tail: combine -> h_all, then 2-layer MLP (FFMA2) ----------------
__global__ void tail_k(const float* __restrict__ fbuf, const float* __restrict__ wp,
                       const float* __restrict__ bm1, const float* __restrict__ Wm2,
                       const float* __restrict__ bm2,
                       float* __restrict__ out, float* __restrict__ logits, int n) {
    __shared__ float Xs[4][16 * 64];
    __shared__ float Wpc[4096];
    __shared__ float Zs[16 * 64];
    int tid = threadIdx.x;
    int cp = tid & 31, ng = tid >> 5;
    int nb = blockIdx.x * 16;
    const float* weffp = wp + 16384;

    const float* fo0 = fbuf + 0 * S;
    const float* fs0 = fbuf + 1 * S;
    const float* fo1 = fbuf + 2 * S;
    const float* fs1 = fbuf + 3 * S;
    const float* fo2 = fbuf + 4 * S;
    const float* fs2 = fbuf + 5 * S;

    int lim64 = (n - nb) * 64;
    if (lim64 > 16 * 64) lim64 = 16 * 64;
    for (int i = tid; i < 16 * 64; i += 256) {
        size_t off = (size_t)nb * 64 + i;
        bool ok = i < lim64;
        Xs[0][i] = ok ? fo0[off] : 0.f;
        Xs[1][i] = ok ? fo1[off] : 0.f;
        Xs[2][i] = ok ? fo2[off] : 0.f;
        Xs[3][i] = ok ? (fs0[off] + fs1[off] + fs2[off]) : 0.f;
    }
    __syncthreads();

    int lim384 = (n - nb) * 384;
    if (lim384 > 6144) lim384 = 6144;
    for (int i = tid; i < lim384; i += 256) {
        int node_l = i / 384;
        int c = i - node_l * 384;
        int seg = c >> 6, cc = c & 63;
        int xi = node_l * 64 + cc;
        float v;
        if (seg == 0)      v = 3.f * Xs[0][xi] - 3.f * Xs[1][xi] + 0.75f * Xs[2][xi];
        else if (seg == 1) v = 3.f * Xs[1][xi] - 1.5f * Xs[2][xi];
        else if (seg == 2) v = 0.75f * Xs[2][xi];
        else               v = 4.f * Xs[3][xi];
        out[(size_t)nb * 384 + i] = v;
    }

    unsigned long long acc0[2] = {0, 0};
    unsigned long long acc1[2] = {0, 0};
    #pragma unroll
    for (int s = 0; s < 4; s++) {
        __syncthreads();
        for (int i = tid; i < 4096; i += 256) Wpc[i] = weffp[s * 4096 + i];
        __syncthreads();
        #pragma unroll 8
        for (int kp = 0; kp < 32; kp++) {
            unsigned long long w0 = *(const unsigned long long*)&Wpc[(kp * 64 + cp) * 2];
            unsigned long long w1 = *(const unsigned long long*)&Wpc[(kp * 64 + cp + 32) * 2];
            #pragma unroll
            for (int j = 0; j < 2; j++) {
                unsigned long long x =
                    *(const unsigned long long*)&Xs[s][(ng * 2 + j) * 64 + 2 * kp];
                FMA_F32X2(acc0[j], x, w0, acc0[j]);
                FMA_F32X2(acc1[j], x, w1, acc1[j]);
            }
        }
    }
    __syncthreads();
    float bb0 = bm1[cp], bb1 = bm1[cp + 32];
    #pragma unroll
    for (int j = 0; j < 2; j++) {
        float z0 = x2lo(acc0[j]) + x2hi(acc0[j]) + bb0;
        float z1 = x2lo(acc1[j]) + x2hi(acc1[j]) + bb1;
        Zs[(ng * 2 + j) * 64 + cp]      = z0 > 0.f ? z0 : 0.f;
        Zs[(ng * 2 + j) * 64 + cp + 32] = z1 > 0.f ? z1 : 0.f;
    }
    __syncthreads();

    if (tid < 32) {
        int node = tid >> 1, jj = tid & 1;
        if (nb + node < n) {
            float sacc = bm2[jj];
            #pragma unroll 8
            for (int c = 0; c < 64; c++) sacc += Zs[node * 64 + c] * Wm2[c * 2 + jj];
            logits[(size_t)(nb + node) * 2 + jj] = sacc;
        }
    }
}

// ---------------- launch (fork-join overlap: CSR build || prep+gemm) ----------------
extern "C" void kernel_launch(void* const* d_in, const int* in_sizes, int n_in,
                              void* d_out, int out_size) {
    const float* x     = (const float*)d_in[0];
    const float* sim_x = (const float*)d_in[1];
    const int*   src   = (const int*)d_in[2];
    const int*   dst   = (const int*)d_in[3];
    const int*   ssrc  = (const int*)d_in[4];
    const int*   sdst  = (const int*)d_in[5];
    const float* W1o   = (const float*)d_in[6];
    const float* b1o   = (const float*)d_in[7];
    const float* W1s   = (const float*)d_in[8];
    const float* b1s   = (const float*)d_in[9];
    const float* Wm1   = (const float*)d_in[10];
    const float* bm1   = (const float*)d_in[11];
    const float* Wm2   = (const float*)d_in[12];
    const float* bm2   = (const float*)d_in[13];

    const int n = NN, ne = NE;

    float *fbuf, *dinv, *wp; __half* gh; int *cnt, *cur, *rs, *csr;
    cudaGetSymbolAddress((void**)&fbuf, d_fbuf);
    cudaGetSymbolAddress((void**)&gh,   d_gh);
    cudaGetSymbolAddress((void**)&dinv, d_dinv);
    cudaGetSymbolAddress((void**)&cnt,  d_cnt);
    cudaGetSymbolAddress((void**)&cur,  d_cur);
    cudaGetSymbolAddress((void**)&rs,   d_rs);
    cudaGetSymbolAddress((void**)&csr,  d_csr);
    cudaGetSymbolAddress((void**)&wp,   d_wp);

    float*  f0base = fbuf + 0 * S;
    float*  f1base = fbuf + 2 * S;
    float*  f2base = fbuf + 4 * S;
    __half* gabase = gh;
    __half* gbbase = gh + 2 * S;

    // lazy host-resource init (streams/events only; no device memory)
    static cudaStream_t sB = nullptr;
    static cudaEvent_t eStart = nullptr, eScan = nullptr, eB = nullptr;
    if (!sB) {
        cudaStreamCreateWithFlags(&sB, cudaStreamNonBlocking);
        cudaEventCreateWithFlags(&eStart, cudaEventDisableTiming);
        cudaEventCreateWithFlags(&eScan,  cudaEventDisableTiming);
        cudaEventCreateWithFlags(&eB,     cudaEventDisableTiming);
    }

    // fork sB off the capture (default) stream
    cudaEventRecord(eStart, 0);
    cudaStreamWaitEvent(sB, eStart, 0);

    // stream0: CSR build chain
    cudaMemsetAsync(cnt, 0, (size_t)2 * NN * sizeof(int), 0);
    int eb2 = (2 * ne + 255) / 256;
    count_k<<<eb2, 256>>>(dst, sdst, cnt, ne);
    scan_k<<<2, 1024>>>(cnt, rs, dinv, cur, n);
    cudaEventRecord(eScan, 0);
    fill_k<<<eb2, 256>>>(src, ssrc, dst, sdst, cur, csr, ne);

    // sB: weight prep (independent), then gemm (needs dinv from scan)
    prep_k<<<128, 256, 0, sB>>>(W1o, W1s, Wm1, wp);
    cudaStreamWaitEvent(sB, eScan, 0);
    dim3 gg((n + 31) / 32, 2);
    gemm_relu_k<<<gg, 256, 0, sB>>>(x, sim_x, wp, b1o, b1s, dinv, f0base, gabase, n);
    cudaEventRecord(eB, sB);

    // join, then serial props + tail on stream0
    cudaStreamWaitEvent(0, eB, 0);
    int pb = (2 * n * 32 + 255) / 256;
    prop_k<<<pb, 256>>>(gabase, f0base, f1base, gbbase, dinv, rs, csr, n, 1);
    prop_k<<<pb, 256>>>(gbbase, f1base, f2base, nullptr, dinv, rs, csr, n, 0);

    float* out    = (float*)d_out;
    float* logits = out + (size_t)n * 384;
    tail_k<<<(n + 15) / 16, 256>>>(fbuf, wp, bm1, Wm2, bm2, out, logits, n);
}

// round 7
// speedup vs baseline: 1.3095x; 1.0154x over previous
#include <cuda_runtime.h>
#include <cuda_bf16.h>
#include <cuda_fp16.h>
#include <stdint.h>

#define NN 50000
#define NE 800000
#define INF 128
#define HID 64
#define S ((size_t)NN * HID)

// packed dual fp32 FMA (sm_103a)
#define FMA_F32X2(d, a, b, c) \
    asm("fma.rn.f32x2 %0, %1, %2, %3;" : "=l"(d) : "l"(a), "l"(b), "l"(c))

__device__ __forceinline__ float x2lo(unsigned long long v) {
    return __uint_as_float((unsigned)(v & 0xffffffffull));
}
__device__ __forceinline__ float x2hi(unsigned long long v) {
    return __uint_as_float((unsigned)(v >> 32));
}

// ---------------- scratch ----------------
// fbuf slots (each S floats): 0=fo0 1=fs0 2=fo1 3=fs1 4=fo2 5=fs2
__device__ float d_fbuf[(size_t)6 * NN * HID];
// fp16 scaled buffers: ga (2 branches) then gb (2 branches)
__device__ __align__(16) __half d_gh[(size_t)4 * NN * HID];
__device__ float d_dinv[2 * NN];
__device__ int   d_cnt [2 * NN];
__device__ int   d_cur [2 * NN];
__device__ int   d_rs  [2 * (NN + 1)];
__device__ int   d_csr [2 * NE];
// interleaved weights: Wp1o (8192) | Wp1s (8192) | Weffp (16384)
__device__ float d_wp[32768];

// ---------------- degree histogram (both branches, int4 loads) ----------------
__global__ void count_k(const int4* __restrict__ d0, const int4* __restrict__ d1,
                        int* __restrict__ cnt, int ne4) {
    int i = blockIdx.x * blockDim.x + threadIdx.x;
    if (i >= 2 * ne4) return;
    int b = (i >= ne4) ? 1 : 0;
    int4 v = b ? d1[i - ne4] : d0[i];
    int* c = cnt + b * NN;
    atomicAdd(&c[v.x], 1);
    atomicAdd(&c[v.y], 1);
    atomicAdd(&c[v.z], 1);
    atomicAdd(&c[v.w], 1);
}

// ---------------- exclusive scan + dinv + cur init (one block per branch) ----------------
__global__ void scan_k(const int* __restrict__ cntA, int* __restrict__ rsA,
                       float* __restrict__ dvA, int* __restrict__ curA, int n) {
    const int* cnt = cntA + blockIdx.x * NN;
    int*       rs  = rsA  + blockIdx.x * (NN + 1);
    float*     dv  = dvA  + blockIdx.x * NN;
    int*       cur = curA + blockIdx.x * NN;
    __shared__ int wsum[32];
    __shared__ int carry_s;
    int tid = threadIdx.x, lane = tid & 31, wid = tid >> 5;
    if (tid == 0) carry_s = 0;
    __syncthreads();
    for (int base = 0; base < n; base += 1024) {
        int i = base + tid;
        int v = (i < n) ? cnt[i] : 0;
        int x = v;
        #pragma unroll
        for (int d = 1; d < 32; d <<= 1) {
            int t = __shfl_up_sync(0xffffffffu, x, d);
            if (lane >= d) x += t;
        }
        if (lane == 31) wsum[wid] = x;
        __syncthreads();
        if (wid == 0) {
            int w = wsum[lane];
            int y = w;
            #pragma unroll
            for (int d = 1; d < 32; d <<= 1) {
                int t = __shfl_up_sync(0xffffffffu, y, d);
                if (lane >= d) y += t;
            }
            wsum[lane] = y - w;
        }
        __syncthreads();
        int excl = x - v + wsum[wid] + carry_s;
        if (i < n) {
            rs[i]  = excl;
            cur[i] = excl;
            dv[i]  = rsqrtf((float)(v > 0 ? v : 1));
        }
        __syncthreads();
        if (tid == 1023) carry_s = excl + v;
        __syncthreads();
    }
    if (threadIdx.x == 0) rs[n] = carry_s;
}

// ---------------- CSR fill (int4 loads, cur preloaded with row starts) ----------------
__global__ void fill_k(const int4* __restrict__ s0, const int4* __restrict__ s1,
                       const int4* __restrict__ d0, const int4* __restrict__ d1,
                       int* __restrict__ cur, int* __restrict__ csr, int ne4) {
    int i = blockIdx.x * blockDim.x + threadIdx.x;
    if (i >= 2 * ne4) return;
    int b = (i >= ne4) ? 1 : 0;
    int j = i - b * ne4;
    int4 dd = b ? d1[j] : d0[j];
    int4 sv = b ? s1[j] : s0[j];
    int* cu = cur + b * NN;
    int* cs = csr + (size_t)b * NE;
    cs[atomicAdd(&cu[dd.x], 1)] = sv.x;
    cs[atomicAdd(&cu[dd.y], 1)] = sv.y;
    cs[atomicAdd(&cu[dd.z], 1)] = sv.z;
    cs[atomicAdd(&cu[dd.w], 1)] = sv.w;
}

// ---------------- weight interleave + combine-fold ----------------
__global__ void prep_k(const float* __restrict__ W1o, const float* __restrict__ W1s,
                       const float* __restrict__ Wm1, float* __restrict__ wp) {
    int i = blockIdx.x * blockDim.x + threadIdx.x;
    if (i >= 32768) return;
    if (i < 16384) {
        int b = i >> 13;
        int pos = i & 8191;
        int j = pos & 1, c = (pos >> 1) & 63, kp = pos >> 7;
        const float* W = b ? W1s : W1o;
        wp[i] = W[(2 * kp + j) * 64 + c];
    } else {
        int pos = i - 16384;
        int j = pos & 1, c = (pos >> 1) & 63, kp = pos >> 7;
        int r = 2 * kp + j;
        int s = r >> 6, kk = r & 63;
        float w0 = Wm1[kk * 64 + c];
        float w1 = Wm1[(64 + kk) * 64 + c];
        float w2 = Wm1[(128 + kk) * 64 + c];
        float v;
        if (s == 0)      v = 3.f * w0;
        else if (s == 1) v = -3.f * w0 + 3.f * w1;
        else if (s == 2) v = 0.75f * w0 - 1.5f * w1 + 0.75f * w2;
        else v = 4.f * (Wm1[(192 + kk) * 64 + c] + Wm1[(256 + kk) * 64 + c] +
                        Wm1[(320 + kk) * 64 + c]);
        wp[i] = v;
    }
}

// ---------------- input GEMM + relu (H only; no dinv dependency) ----------------
__global__ void gemm_relu_k(const float* __restrict__ X0, const float* __restrict__ X1,
                            const float* __restrict__ wp,
                            const float* __restrict__ b0, const float* __restrict__ b1,
                            float* __restrict__ f0base, int n) {
    __shared__ float Xs[32 * 128];
    __shared__ float Wpc[4096];
    int by = blockIdx.y;
    const float* X  = by ? X1 : X0;
    const float* Wp = wp + by * 8192;
    const float* b  = by ? b1 : b0;
    float* H = f0base + (size_t)by * S;

    int tid = threadIdx.x;
    int cp = tid & 31, ng = tid >> 5;
    int nb = blockIdx.x * 32;

    int lim = (n - nb) * 128;
    if (lim > 32 * 128) lim = 32 * 128;
    for (int i = tid; i < 32 * 128; i += 256)
        Xs[i] = (i < lim) ? X[(size_t)nb * 128 + i] : 0.f;

    unsigned long long acc0[4] = {0, 0, 0, 0};
    unsigned long long acc1[4] = {0, 0, 0, 0};

    #pragma unroll
    for (int ch = 0; ch < 2; ch++) {
        __syncthreads();
        for (int i = tid; i < 4096; i += 256) Wpc[i] = Wp[ch * 4096 + i];
        __syncthreads();
        #pragma unroll 8
        for (int kp = 0; kp < 32; kp++) {
            unsigned long long w0 = *(const unsigned long long*)&Wpc[(kp * 64 + cp) * 2];
            unsigned long long w1 = *(const unsigned long long*)&Wpc[(kp * 64 + cp + 32) * 2];
            #pragma unroll
            for (int j = 0; j < 4; j++) {
                unsigned long long x =
                    *(const unsigned long long*)&Xs[(ng * 4 + j) * 128 + ch * 64 + 2 * kp];
                FMA_F32X2(acc0[j], x, w0, acc0[j]);
                FMA_F32X2(acc1[j], x, w1, acc1[j]);
            }
        }
    }

    float bb0 = b[cp], bb1 = b[cp + 32];
    #pragma unroll
    for (int j = 0; j < 4; j++) {
        int node = nb + ng * 4 + j;
        if (node < n) {
            float v0 = x2lo(acc0[j]) + x2hi(acc0[j]) + bb0;
            float v1 = x2lo(acc1[j]) + x2hi(acc1[j]) + bb1;
            size_t base = (size_t)node * 64;
            H[base + cp]      = v0 > 0.f ? v0 : 0.f;
            H[base + cp + 32] = v1 > 0.f ? v1 : 0.f;
        }
    }
}

// ---------------- g(fp16) = H * dinv (covers both branches; H slots contiguous) ----------------
__global__ void scale_k(const float4* __restrict__ H, const float* __restrict__ dinv_all,
                        uint4* __restrict__ G, int total) {   // total = 2*S/8
    int i = blockIdx.x * blockDim.x + threadIdx.x;
    if (i >= total) return;
    float dv = dinv_all[i >> 3];
    float4 a = H[2 * i], b = H[2 * i + 1];
    __half2 h0 = __floats2half2_rn(a.x * dv, a.y * dv);
    __half2 h1 = __floats2half2_rn(a.z * dv, a.w * dv);
    __half2 h2 = __floats2half2_rn(b.x * dv, b.y * dv);
    __half2 h3 = __floats2half2_rn(b.z * dv, b.w * dv);
    uint4 o;
    o.x = *(unsigned*)&h0; o.y = *(unsigned*)&h1;
    o.z = *(unsigned*)&h2; o.w = *(unsigned*)&h3;
    G[i] = o;
}

// ---------------- propagation step (fp16 gather, predicated full unroll) ----------------
__global__ void prop_k(const __half* __restrict__ gin, const float* __restrict__ fin,
                       float* __restrict__ fout, __half* __restrict__ gout,
                       const float* __restrict__ dinv_all, const int* __restrict__ rs_all,
                       const int* __restrict__ csr_all, int n, int writeG) {
    int gw = (blockIdx.x * blockDim.x + threadIdx.x) >> 5;
    int lane = threadIdx.x & 31;
    if (gw >= 2 * n) return;
    int b = (gw >= n) ? 1 : 0;
    int w = gw - b * n;
    const __half2* g2  = (const __half2*)(gin + (size_t)b * S);
    const int*     rs  = rs_all + b * (NN + 1);
    const int*     csr = csr_all + (size_t)b * NE;
    int beg = rs[w], end = rs[w + 1];
    float2 a = make_float2(0.f, 0.f);
    for (int base = beg; base < end; base += 32) {
        int idx = base + lane;
        int sreg = (idx < end) ? csr[idx] : 0;
        int cnt = end - base;
        if (cnt > 32) cnt = 32;
        #pragma unroll
        for (int t8 = 0; t8 < 4; t8++) {
            if (t8 * 8 >= cnt) break;
            #pragma unroll
            for (int tt = 0; tt < 8; tt++) {
                int t = t8 * 8 + tt;
                int ss = __shfl_sync(0xffffffffu, sreg, t);
                if (t < cnt) {
                    float2 v = __half22float2(g2[(size_t)ss * 32 + lane]);
                    a.x += v.x; a.y += v.y;
                }
            }
        }
    }
    float dvv = dinv_all[b * NN + w];
    const float2* f2 = (const float2*)(fin + (size_t)b * S);
    float2 fv = f2[(size_t)w * 32 + lane];
    float2 o;
    o.x = fv.x - a.x * dvv;
    o.y = fv.y - a.y * dvv;
    ((float2*)(fout + (size_t)b * S))[(size_t)w * 32 + lane] = o;
    if (writeG) {
        float2 go;
        go.x = o.x * dvv; go.y = o.y * dvv;
        ((__half2*)(gout + (size_t)b * S))[(size_t)w * 32 + lane] = __float22half2_rn(go);
    }
}

// ---------------- fused tail: combine -> h_all, then 2-layer MLP (FFMA2) ----------------
__global__ void tail_k(const float* __restrict__ fbuf, const float* __restrict__ wp,
                       const float* __restrict__ bm1, const float* __restrict__ Wm2,
                       const float* __restrict__ bm2,
                       float* __restrict__ out, float* __restrict__ logits, int n) {
    __shared__ float Xs[4][16 * 64];
    __shared__ float Wpc[4096];
    __shared__ float Zs[16 * 68];   // padded stride to avoid bank conflicts
    int tid = threadIdx.x;
    int cp = tid & 31, ng = tid >> 5;
    int nb = blockIdx.x * 16;
    const float* weffp = wp + 16384;

    const float* fo0 = fbuf + 0 * S;
    const float* fs0 = fbuf + 1 * S;
    const float* fo1 = fbuf + 2 * S;
    const float* fs1 = fbuf + 3 * S;
    const float* fo2 = fbuf + 4 * S;
    const float* fs2 = fbuf + 5 * S;

    int lim64 = (n - nb) * 64;
    if (lim64 > 16 * 64) lim64 = 16 * 64;
    for (int i = tid; i < 16 * 64; i += 256) {
        size_t off = (size_t)nb * 64 + i;
        bool ok = i < lim64;
        Xs[0][i] = ok ? fo0[off] : 0.f;
        Xs[1][i] = ok ? fo1[off] : 0.f;
        Xs[2][i] = ok ? fo2[off] : 0.f;
        Xs[3][i] = ok ? (fs0[off] + fs1[off] + fs2[off]) : 0.f;
    }
    __syncthreads();

    int lim384 = (n - nb) * 384;
    if (lim384 > 6144) lim384 = 6144;
    for (int i = tid; i < lim384; i += 256) {
        int node_l = i / 384;
        int c = i - node_l * 384;
        int seg = c >> 6, cc = c & 63;
        int xi = node_l * 64 + cc;
        float v;
        if (seg == 0)      v = 3.f * Xs[0][xi] - 3.f * Xs[1][xi] + 0.75f * Xs[2][xi];
        else if (seg == 1) v = 3.f * Xs[1][xi] - 1.5f * Xs[2][xi];
        else if (seg == 2) v = 0.75f * Xs[2][xi];
        else               v = 4.f * Xs[3][xi];
        out[(size_t)nb * 384 + i] = v;
    }

    unsigned long long acc0[2] = {0, 0};
    unsigned long long acc1[2] = {0, 0};
    #pragma unroll
    for (int s = 0; s < 4; s++) {
        __syncthreads();
        for (int i = tid; i < 4096; i += 256) Wpc[i] = weffp[s * 4096 + i];
        __syncthreads();
        #pragma unroll 8
        for (int kp = 0; kp < 32; kp++) {
            unsigned long long w0 = *(const unsigned long long*)&Wpc[(kp * 64 + cp) * 2];
            unsigned long long w1 = *(const unsigned long long*)&Wpc[(kp * 64 + cp + 32) * 2];
            #pragma unroll
            for (int j = 0; j < 2; j++) {
                unsigned long long x =
                    *(const unsigned long long*)&Xs[s][(ng * 2 + j) * 64 + 2 * kp];
                FMA_F32X2(acc0[j], x, w0, acc0[j]);
                FMA_F32X2(acc1[j], x, w1, acc1[j]);
            }
        }
    }
    __syncthreads();
    float bb0 = bm1[cp], bb1 = bm1[cp + 32];
    #pragma unroll
    for (int j = 0; j < 2; j++) {
        float z0 = x2lo(acc0[j]) + x2hi(acc0[j]) + bb0;
        float z1 = x2lo(acc1[j]) + x2hi(acc1[j]) + bb1;
        Zs[(ng * 2 + j) * 68 + cp]      = z0 > 0.f ? z0 : 0.f;
        Zs[(ng * 2 + j) * 68 + cp + 32] = z1 > 0.f ? z1 : 0.f;
    }
    __syncthreads();

    // layer 2: 128 threads, 4 threads per (node, jj) output, shfl-reduced
    if (tid < 128) {
        int out_id = tid >> 2;        // 0..31
        int node = out_id >> 1, jj = out_id & 1;
        int q = tid & 3;              // 16-col slice
        float sacc = 0.f;
        #pragma unroll
        for (int c = 0; c < 16; c++) {
            int cc = q * 16 + c;
            sacc += Zs[node * 68 + cc] * Wm2[cc * 2 + jj];
        }
        sacc += __shfl_down_sync(0xffffffffu, sacc, 2);
        sacc += __shfl_down_sync(0xffffffffu, sacc, 1);
        if (q == 0 && nb + node < n)
            logits[(size_t)(nb + node) * 2 + jj] = sacc + bm2[jj];
    }
}

// ---------------- launch (fork-join: CSR build || prep+gemm from t0) ----------------
extern "C" void kernel_launch(void* const* d_in, const int* in_sizes, int n_in,
                              void* d_out, int out_size) {
    const float* x     = (const float*)d_in[0];
    const float* sim_x = (const float*)d_in[1];
    const int*   src   = (const int*)d_in[2];
    const int*   dst   = (const int*)d_in[3];
    const int*   ssrc  = (const int*)d_in[4];
    const int*   sdst  = (const int*)d_in[5];
    const float* W1o   = (const float*)d_in[6];
    const float* b1o   = (const float*)d_in[7];
    const float* W1s   = (const float*)d_in[8];
    const float* b1s   = (const float*)d_in[9];
    const float* Wm1   = (const float*)d_in[10];
    const float* bm1   = (const float*)d_in[11];
    const float* Wm2   = (const float*)d_in[12];
    const float* bm2   = (const float*)d_in[13];

    const int n = NN, ne = NE;

    float *fbuf, *dinv, *wp; __half* gh; int *cnt, *cur, *rs, *csr;
    cudaGetSymbolAddress((void**)&fbuf, d_fbuf);
    cudaGetSymbolAddress((void**)&gh,   d_gh);
    cudaGetSymbolAddress((void**)&dinv, d_dinv);
    cudaGetSymbolAddress((void**)&cnt,  d_cnt);
    cudaGetSymbolAddress((void**)&cur,  d_cur);
    cudaGetSymbolAddress((void**)&rs,   d_rs);
    cudaGetSymbolAddress((void**)&csr,  d_csr);
    cudaGetSymbolAddress((void**)&wp,   d_wp);

    float*  f0base = fbuf + 0 * S;
    float*  f1base = fbuf + 2 * S;
    float*  f2base = fbuf + 4 * S;
    __half* gabase = gh;
    __half* gbbase = gh + 2 * S;

    static cudaStream_t sB = nullptr;
    static cudaEvent_t eStart = nullptr, eScan = nullptr, eB = nullptr;
    if (!sB) {
        cudaStreamCreateWithFlags(&sB, cudaStreamNonBlocking);
        cudaEventCreateWithFlags(&eStart, cudaEventDisableTiming);
        cudaEventCreateWithFlags(&eScan,  cudaEventDisableTiming);
        cudaEventCreateWithFlags(&eB,     cudaEventDisableTiming);
    }

    cudaEventRecord(eStart, 0);
    cudaStreamWaitEvent(sB, eStart, 0);

    // stream0: CSR build chain
    cudaMemsetAsync(cnt, 0, (size_t)2 * NN * sizeof(int), 0);
    int ne4 = ne / 4;
    int eb4 = (2 * ne4 + 255) / 256;
    count_k<<<eb4, 256>>>((const int4*)dst, (const int4*)sdst, cnt, ne4);
    scan_k<<<2, 1024>>>(cnt, rs, dinv, cur, n);
    cudaEventRecord(eScan, 0);
    fill_k<<<eb4, 256>>>((const int4*)src, (const int4*)ssrc,
                         (const int4*)dst, (const int4*)sdst, cur, csr, ne4);

    // sB: prep + gemm (input-only deps) from t0, then scale after scan
    prep_k<<<128, 256, 0, sB>>>(W1o, W1s, Wm1, wp);
    dim3 gg((n + 31) / 32, 2);
    gemm_relu_k<<<gg, 256, 0, sB>>>(x, sim_x, wp, b1o, b1s, f0base, n);
    cudaStreamWaitEvent(sB, eScan, 0);
    int total8 = (int)(2 * S / 8);
    scale_k<<<(total8 + 255) / 256, 256, 0, sB>>>((const float4*)f0base, dinv,
                                                  (uint4*)gabase, total8);
    cudaEventRecord(eB, sB);

    // join, then serial props + tail on stream0
    cudaStreamWaitEvent(0, eB, 0);
    int pb = (2 * n * 32 + 255) / 256;
    prop_k<<<pb, 256>>>(gabase, f0base, f1base, gbbase, dinv, rs, csr, n, 1);
    prop_k<<<pb, 256>>>(gbbase, f1base, f2base, nullptr, dinv, rs, csr, n, 0);

    float* out    = (float*)d_out;
    float* logits = out + (size_t)n * 384;
    tail_k<<<(n + 15) / 16, 256>>>(fbuf, wp, bm1, Wm2, bm2, out, logits, n);
}

// round 9
// speedup vs baseline: 1.3409x; 1.0239x over previous
#include <cuda_runtime.h>
#include <cuda_bf16.h>
#include <cuda_fp16.h>
#include <stdint.h>

#define NN 50000
#define NE 800000
#define INF 128
#define HID 64
#define S ((size_t)NN * HID)

// packed dual fp32 FMA (sm_103a)
#define FMA_F32X2(d, a, b, c) \
    asm("fma.rn.f32x2 %0, %1, %2, %3;" : "=l"(d) : "l"(a), "l"(b), "l"(c))

__device__ __forceinline__ float x2lo(unsigned long long v) {
    return __uint_as_float((unsigned)(v & 0xffffffffull));
}
__device__ __forceinline__ float x2hi(unsigned long long v) {
    return __uint_as_float((unsigned)(v >> 32));
}

// ---------------- scratch ----------------
// fbuf slots (each S floats): 0=fo0 1=fs0 2=fo1 3=fs1 4=fo2 5=fs2
__device__ float d_fbuf[(size_t)6 * NN * HID];
// fp16 scaled buffers: ga (2 branches) then gb (2 branches)
__device__ __align__(16) __half d_gh[(size_t)4 * NN * HID];
__device__ float d_dinv[2 * NN];
__device__ int   d_cnt [2 * NN];
__device__ int   d_cur [2 * NN];
__device__ int   d_rs  [2 * (NN + 1)];
__device__ int   d_csr [2 * NE];
__device__ float d_weff[16384];   // tail layer-1 effective weights, interleaved

// ---------------- degree histogram (both branches, int4 loads) ----------------
__global__ void count_k(const int4* __restrict__ d0, const int4* __restrict__ d1,
                        int* __restrict__ cnt, int ne4) {
    int i = blockIdx.x * blockDim.x + threadIdx.x;
    if (i >= 2 * ne4) return;
    int b = (i >= ne4) ? 1 : 0;
    int4 v = b ? d1[i - ne4] : d0[i];
    int* c = cnt + b * NN;
    atomicAdd(&c[v.x], 1);
    atomicAdd(&c[v.y], 1);
    atomicAdd(&c[v.z], 1);
    atomicAdd(&c[v.w], 1);
}

// ---------------- exclusive scan + dinv + cur init (one block per branch) ----------------
__global__ void scan_k(const int* __restrict__ cntA, int* __restrict__ rsA,
                       float* __restrict__ dvA, int* __restrict__ curA, int n) {
    const int* cnt = cntA + blockIdx.x * NN;
    int*       rs  = rsA  + blockIdx.x * (NN + 1);
    float*     dv  = dvA  + blockIdx.x * NN;
    int*       cur = curA + blockIdx.x * NN;
    __shared__ int wsum[32];
    __shared__ int carry_s;
    int tid = threadIdx.x, lane = tid & 31, wid = tid >> 5;
    if (tid == 0) carry_s = 0;
    __syncthreads();
    for (int base = 0; base < n; base += 1024) {
        int i = base + tid;
        int v = (i < n) ? cnt[i] : 0;
        int x = v;
        #pragma unroll
        for (int d = 1; d < 32; d <<= 1) {
            int t = __shfl_up_sync(0xffffffffu, x, d);
            if (lane >= d) x += t;
        }
        if (lane == 31) wsum[wid] = x;
        __syncthreads();
        if (wid == 0) {
            int w = wsum[lane];
            int y = w;
            #pragma unroll
            for (int d = 1; d < 32; d <<= 1) {
                int t = __shfl_up_sync(0xffffffffu, y, d);
                if (lane >= d) y += t;
            }
            wsum[lane] = y - w;
        }
        __syncthreads();
        int excl = x - v + wsum[wid] + carry_s;
        if (i < n) {
            rs[i]  = excl;
            cur[i] = excl;
            dv[i]  = rsqrtf((float)(v > 0 ? v : 1));
        }
        __syncthreads();
        if (tid == 1023) carry_s = excl + v;
        __syncthreads();
    }
    if (threadIdx.x == 0) rs[n] = carry_s;
}

// ---------------- CSR fill (int4 loads, cur preloaded with row starts) ----------------
__global__ void fill_k(const int4* __restrict__ s0, const int4* __restrict__ s1,
                       const int4* __restrict__ d0, const int4* __restrict__ d1,
                       int* __restrict__ cur, int* __restrict__ csr, int ne4) {
    int i = blockIdx.x * blockDim.x + threadIdx.x;
    if (i >= 2 * ne4) return;
    int b = (i >= ne4) ? 1 : 0;
    int j = i - b * ne4;
    int4 dd = b ? d1[j] : d0[j];
    int4 sv = b ? s1[j] : s0[j];
    int* cu = cur + b * NN;
    int* cs = csr + (size_t)b * NE;
    cs[atomicAdd(&cu[dd.x], 1)] = sv.x;
    cs[atomicAdd(&cu[dd.y], 1)] = sv.y;
    cs[atomicAdd(&cu[dd.z], 1)] = sv.z;
    cs[atomicAdd(&cu[dd.w], 1)] = sv.w;
}

// ---------------- input GEMM + relu + fused fp16 dinv-scale ----------------
// W interleave done during smem stage (no prep dependency).
__global__ void gemm_relu_k(const float* __restrict__ X0, const float* __restrict__ X1,
                            const float* __restrict__ W0g, const float* __restrict__ W1g,
                            const float* __restrict__ b0, const float* __restrict__ b1,
                            const float* __restrict__ dinv_all,
                            float* __restrict__ f0base, __half* __restrict__ gbase, int n) {
    __shared__ float Xs[32 * 128];
    __shared__ float Wpc[4096];    // [32kp][64c][2]
    int by = blockIdx.y;
    const float* X  = by ? X1 : X0;
    const float* W  = by ? W1g : W0g;
    const float* b  = by ? b1 : b0;
    const float* dv = dinv_all + by * NN;
    float*  H = f0base + (size_t)by * S;
    __half* G = gbase  + (size_t)by * S;

    int tid = threadIdx.x;
    int cp = tid & 31, ng = tid >> 5;
    int nb = blockIdx.x * 32;

    int lim = (n - nb) * 128;
    if (lim > 32 * 128) lim = 32 * 128;
    for (int i = tid; i < 32 * 128; i += 256)
        Xs[i] = (i < lim) ? X[(size_t)nb * 128 + i] : 0.f;

    unsigned long long acc0[4] = {0, 0, 0, 0};
    unsigned long long acc1[4] = {0, 0, 0, 0};

    #pragma unroll
    for (int ch = 0; ch < 2; ch++) {
        __syncthreads();
        // interleaved stage: Wpc[(kp*64+c)*2 + j] = W[(ch*64 + 2kp + j)*64 + c]
        for (int i = tid; i < 4096; i += 256) {
            int j = i & 1, c = (i >> 1) & 63, kp = i >> 7;
            Wpc[i] = W[(size_t)(ch * 64 + 2 * kp + j) * 64 + c];
        }
        __syncthreads();
        #pragma unroll 8
        for (int kp = 0; kp < 32; kp++) {
            unsigned long long w0 = *(const unsigned long long*)&Wpc[(kp * 64 + cp) * 2];
            unsigned long long w1 = *(const unsigned long long*)&Wpc[(kp * 64 + cp + 32) * 2];
            #pragma unroll
            for (int j = 0; j < 4; j++) {
                unsigned long long x =
                    *(const unsigned long long*)&Xs[(ng * 4 + j) * 128 + ch * 64 + 2 * kp];
                FMA_F32X2(acc0[j], x, w0, acc0[j]);
                FMA_F32X2(acc1[j], x, w1, acc1[j]);
            }
        }
    }

    float bb0 = b[cp], bb1 = b[cp + 32];
    #pragma unroll
    for (int j = 0; j < 4; j++) {
        int node = nb + ng * 4 + j;
        if (node < n) {
            float dvv = dv[node];
            float v0 = x2lo(acc0[j]) + x2hi(acc0[j]) + bb0;
            float v1 = x2lo(acc1[j]) + x2hi(acc1[j]) + bb1;
            v0 = v0 > 0.f ? v0 : 0.f;
            v1 = v1 > 0.f ? v1 : 0.f;
            size_t base = (size_t)node * 64;
            H[base + cp]      = v0;
            H[base + cp + 32] = v1;
            G[base + cp]      = __float2half_rn(v0 * dvv);
            G[base + cp + 32] = __float2half_rn(v1 * dvv);
        }
    }
}

// ---------------- tail weight prep (combine-fold, interleaved) ----------------
__global__ void prep_k(const float* __restrict__ Wm1, float* __restrict__ weff) {
    int i = blockIdx.x * blockDim.x + threadIdx.x;
    if (i >= 16384) return;
    int j = i & 1, c = (i >> 1) & 63, kp = i >> 7;
    int r = 2 * kp + j;
    int s = r >> 6, kk = r & 63;
    float w0 = Wm1[kk * 64 + c];
    float w1 = Wm1[(64 + kk) * 64 + c];
    float w2 = Wm1[(128 + kk) * 64 + c];
    float v;
    if (s == 0)      v = 3.f * w0;
    else if (s == 1) v = -3.f * w0 + 3.f * w1;
    else if (s == 2) v = 0.75f * w0 - 1.5f * w1 + 0.75f * w2;
    else v = 4.f * (Wm1[(192 + kk) * 64 + c] + Wm1[(256 + kk) * 64 + c] +
                    Wm1[(320 + kk) * 64 + c]);
    weff[i] = v;
}

// ---------------- propagation: 4 edges in flight via 8-lane groups ----------------
// Each group of 8 lanes gathers one edge's full 128-B fp16 row (uint4/lane).
// Butterfly reduce across groups at the end; lanes 0-7 do the epilogue.
__global__ void prop_k(const __half* __restrict__ gin, const float* __restrict__ fin,
                       float* __restrict__ fout, __half* __restrict__ gout,
                       const float* __restrict__ dinv_all, const int* __restrict__ rs_all,
                       const int* __restrict__ csr_all, int n, int writeG) {
    int gw = (blockIdx.x * blockDim.x + threadIdx.x) >> 5;
    int lane = threadIdx.x & 31;
    if (gw >= 2 * n) return;
    int b = (gw >= n) ? 1 : 0;
    int w = gw - b * n;
    const __half* gp  = gin + (size_t)b * S;
    const int*    rs  = rs_all + b * (NN + 1);
    const int*    csr = csr_all + (size_t)b * NE;
    int beg = rs[w], end = rs[w + 1];

    int grp = lane >> 3;          // 0..3  (edge slot within batch)
    int sub = lane & 7;           // 0..7  (16-B piece within row)

    float a[8];
    #pragma unroll
    for (int i = 0; i < 8; i++) a[i] = 0.f;

    for (int base = beg; base < end; base += 32) {
        int idx = base + lane;
        int sreg = (idx < end) ? __ldg(&csr[idx]) : 0;
        int cnt = end - base;
        if (cnt > 32) cnt = 32;
        #pragma unroll
        for (int tb = 0; tb < 8; tb++) {
            if (tb * 4 >= cnt) break;
            int t = tb * 4 + grp;
            int ss = __shfl_sync(0xffffffffu, sreg, t);
            if (t < cnt) {
                uint4 v = *(const uint4*)(gp + (size_t)ss * 64 + sub * 8);
                const __half2* h = (const __half2*)&v;
                #pragma unroll
                for (int q = 0; q < 4; q++) {
                    float2 f = __half22float2(h[q]);
                    a[2 * q]     += f.x;
                    a[2 * q + 1] += f.y;
                }
            }
        }
    }

    // reduce the 4 groups (cols live at 8*sub + i)
    #pragma unroll
    for (int i = 0; i < 8; i++) {
        a[i] += __shfl_xor_sync(0xffffffffu, a[i], 8);
        a[i] += __shfl_xor_sync(0xffffffffu, a[i], 16);
    }

    if (lane < 8) {
        float dvv = dinv_all[b * NN + w];
        const float4* f4 = (const float4*)(fin + (size_t)b * S + (size_t)w * 64 + lane * 8);
        float4 fv0 = f4[0], fv1 = f4[1];
        float4 o0, o1;
        o0.x = fv0.x - a[0] * dvv;
        o0.y = fv0.y - a[1] * dvv;
        o0.z = fv0.z - a[2] * dvv;
        o0.w = fv0.w - a[3] * dvv;
        o1.x = fv1.x - a[4] * dvv;
        o1.y = fv1.y - a[5] * dvv;
        o1.z = fv1.z - a[6] * dvv;
        o1.w = fv1.w - a[7] * dvv;
        float4* fo = (float4*)(fout + (size_t)b * S + (size_t)w * 64 + lane * 8);
        fo[0] = o0;
        fo[1] = o1;
        if (writeG) {
            __half2 h0 = __floats2half2_rn(o0.x * dvv, o0.y * dvv);
            __half2 h1 = __floats2half2_rn(o0.z * dvv, o0.w * dvv);
            __half2 h2 = __floats2half2_rn(o1.x * dvv, o1.y * dvv);
            __half2 h3 = __floats2half2_rn(o1.z * dvv, o1.w * dvv);
            uint4 gv;
            gv.x = *(unsigned*)&h0; gv.y = *(unsigned*)&h1;
            gv.z = *(unsigned*)&h2; gv.w = *(unsigned*)&h3;
            *(uint4*)(gout + (size_t)b * S + (size_t)w * 64 + lane * 8) = gv;
        }
    }
}

// ---------------- fused tail: combine -> h_all, then 2-layer MLP (FFMA2) ----------------
__global__ void tail_k(const float* __restrict__ fbuf, const float* __restrict__ weffp,
                       const float* __restrict__ bm1, const float* __restrict__ Wm2,
                       const float* __restrict__ bm2,
                       float* __restrict__ out, float* __restrict__ logits, int n) {
    __shared__ float Xs[4][16 * 64];
    __shared__ float Wpc[4096];
    __shared__ float Zs[16 * 68];
    int tid = threadIdx.x;
    int cp = tid & 31, ng = tid >> 5;
    int nb = blockIdx.x * 16;

    const float* fo0 = fbuf + 0 * S;
    const float* fs0 = fbuf + 1 * S;
    const float* fo1 = fbuf + 2 * S;
    const float* fs1 = fbuf + 3 * S;
    const float* fo2 = fbuf + 4 * S;
    const float* fs2 = fbuf + 5 * S;

    int lim64 = (n - nb) * 64;
    if (lim64 > 16 * 64) lim64 = 16 * 64;
    for (int i = tid; i < 16 * 64; i += 256) {
        size_t off = (size_t)nb * 64 + i;
        bool ok = i < lim64;
        Xs[0][i] = ok ? fo0[off] : 0.f;
        Xs[1][i] = ok ? fo1[off] : 0.f;
        Xs[2][i] = ok ? fo2[off] : 0.f;
        Xs[3][i] = ok ? (fs0[off] + fs1[off] + fs2[off]) : 0.f;
    }
    __syncthreads();

    int lim384 = (n - nb) * 384;
    if (lim384 > 6144) lim384 = 6144;
    for (int i = tid; i < lim384; i += 256) {
        int node_l = i / 384;
        int c = i - node_l * 384;
        int seg = c >> 6, cc = c & 63;
        int xi = node_l * 64 + cc;
        float v;
        if (seg == 0)      v = 3.f * Xs[0][xi] - 3.f * Xs[1][xi] + 0.75f * Xs[2][xi];
        else if (seg == 1) v = 3.f * Xs[1][xi] - 1.5f * Xs[2][xi];
        else if (seg == 2) v = 0.75f * Xs[2][xi];
        else               v = 4.f * Xs[3][xi];
        out[(size_t)nb * 384 + i] = v;
    }

    unsigned long long acc0[2] = {0, 0};
    unsigned long long acc1[2] = {0, 0};
    #pragma unroll
    for (int s = 0; s < 4; s++) {
        __syncthreads();
        for (int i = tid; i < 4096; i += 256) Wpc[i] = weffp[s * 4096 + i];
        __syncthreads();
        #pragma unroll 8
        for (int kp = 0; kp < 32; kp++) {
            unsigned long long w0 = *(const unsigned long long*)&Wpc[(kp * 64 + cp) * 2];
            unsigned long long w1 = *(const unsigned long long*)&Wpc[(kp * 64 + cp + 32) * 2];
            #pragma unroll
            for (int j = 0; j < 2; j++) {
                unsigned long long x =
                    *(const unsigned long long*)&Xs[s][(ng * 2 + j) * 64 + 2 * kp];
                FMA_F32X2(acc0[j], x, w0, acc0[j]);
                FMA_F32X2(acc1[j], x, w1, acc1[j]);
            }
        }
    }
    __syncthreads();
    float bb0 = bm1[cp], bb1 = bm1[cp + 32];
    #pragma unroll
    for (int j = 0; j < 2; j++) {
        float z0 = x2lo(acc0[j]) + x2hi(acc0[j]) + bb0;
        float z1 = x2lo(acc1[j]) + x2hi(acc1[j]) + bb1;
        Zs[(ng * 2 + j) * 68 + cp]      = z0 > 0.f ? z0 : 0.f;
        Zs[(ng * 2 + j) * 68 + cp + 32] = z1 > 0.f ? z1 : 0.f;
    }
    __syncthreads();

    if (tid < 128) {
        int out_id = tid >> 2;
        int node = out_id >> 1, jj = out_id & 1;
        int q = tid & 3;
        float sacc = 0.f;
        #pragma unroll
        for (int c = 0; c < 16; c++) {
            int cc = q * 16 + c;
            sacc += Zs[node * 68 + cc] * Wm2[cc * 2 + jj];
        }
        sacc += __shfl_down_sync(0xffffffffu, sacc, 2);
        sacc += __shfl_down_sync(0xffffffffu, sacc, 1);
        if (q == 0 && nb + node < n)
            logits[(size_t)(nb + node) * 2 + jj] = sacc + bm2[jj];
    }
}

// ---------------- launch ----------------
extern "C" void kernel_launch(void* const* d_in, const int* in_sizes, int n_in,
                              void* d_out, int out_size) {
    const float* x     = (const float*)d_in[0];
    const float* sim_x = (const float*)d_in[1];
    const int*   src   = (const int*)d_in[2];
    const int*   dst   = (const int*)d_in[3];
    const int*   ssrc  = (const int*)d_in[4];
    const int*   sdst  = (const int*)d_in[5];
    const float* W1o   = (const float*)d_in[6];
    const float* b1o   = (const float*)d_in[7];
    const float* W1s   = (const float*)d_in[8];
    const float* b1s   = (const float*)d_in[9];
    const float* Wm1   = (const float*)d_in[10];
    const float* bm1   = (const float*)d_in[11];
    const float* Wm2   = (const float*)d_in[12];
    const float* bm2   = (const float*)d_in[13];

    const int n = NN, ne = NE;

    float *fbuf, *dinv, *weff; __half* gh; int *cnt, *cur, *rs, *csr;
    cudaGetSymbolAddress((void**)&fbuf, d_fbuf);
    cudaGetSymbolAddress((void**)&gh,   d_gh);
    cudaGetSymbolAddress((void**)&dinv, d_dinv);
    cudaGetSymbolAddress((void**)&cnt,  d_cnt);
    cudaGetSymbolAddress((void**)&cur,  d_cur);
    cudaGetSymbolAddress((void**)&rs,   d_rs);
    cudaGetSymbolAddress((void**)&csr,  d_csr);
    cudaGetSymbolAddress((void**)&weff, d_weff);

    float*  f0base = fbuf + 0 * S;
    float*  f1base = fbuf + 2 * S;
    float*  f2base = fbuf + 4 * S;
    __half* gabase = gh;
    __half* gbbase = gh + 2 * S;

    static cudaStream_t sB = nullptr;
    static cudaEvent_t eStart = nullptr, eScan = nullptr, eB = nullptr;
    if (!sB) {
        cudaStreamCreateWithFlags(&sB, cudaStreamNonBlocking);
        cudaEventCreateWithFlags(&eStart, cudaEventDisableTiming);
        cudaEventCreateWithFlags(&eScan,  cudaEventDisableTiming);
        cudaEventCreateWithFlags(&eB,     cudaEventDisableTiming);
    }

    cudaEventRecord(eStart, 0);
    cudaStreamWaitEvent(sB, eStart, 0);

    // stream0: CSR build chain  (kernels #1..#3)
    cudaMemsetAsync(cnt, 0, (size_t)2 * NN * sizeof(int), 0);
    int ne4 = ne / 4;
    int eb4 = (2 * ne4 + 255) / 256;
    count_k<<<eb4, 256>>>((const int4*)dst, (const int4*)sdst, cnt, ne4);
    scan_k<<<2, 1024>>>(cnt, rs, dinv, cur, n);
    cudaEventRecord(eScan, 0);
    fill_k<<<eb4, 256>>>((const int4*)src, (const int4*)ssrc,
                         (const int4*)dst, (const int4*)sdst, cur, csr, ne4);

    // sB: gemm (#4 — profiled slot) waits only on scan; prep (#5) independent
    cudaStreamWaitEvent(sB, eScan, 0);
    dim3 gg((n + 31) / 32, 2);
    gemm_relu_k<<<gg, 256, 0, sB>>>(x, sim_x, W1o, W1s, b1o, b1s, dinv,
                                    f0base, gabase, n);
    prep_k<<<64, 256, 0, sB>>>(Wm1, weff);
    cudaEventRecord(eB, sB);

    // join, then serial props + tail on stream0
    cudaStreamWaitEvent(0, eB, 0);
    int pb = (2 * n * 32 + 255) / 256;
    prop_k<<<pb, 256>>>(gabase, f0base, f1base, gbbase, dinv, rs, csr, n, 1);
    prop_k<<<pb, 256>>>(gbbase, f1base, f2base, nullptr, dinv, rs, csr, n, 0);

    float* out    = (float*)d_out;
    float* logits = out + (size_t)n * 384;
    tail_k<<<(n + 15) / 16, 256>>>(fbuf, weff, bm1, Wm2, bm2, out, logits, n);
}

// round 10
// speedup vs baseline: 1.4346x; 1.0699x over previous
#include <cuda_runtime.h>
#include <cuda_bf16.h>
#include <cuda_fp16.h>
#include <stdint.h>

#define NN 50000
#define NE 800000
#define INF 128
#define HID 64
#define S ((size_t)NN * HID)

// packed dual fp32 FMA (sm_103a)
#define FMA_F32X2(d, a, b, c) \
    asm("fma.rn.f32x2 %0, %1, %2, %3;" : "=l"(d) : "l"(a), "l"(b), "l"(c))

__device__ __forceinline__ float x2lo(unsigned long long v) {
    return __uint_as_float((unsigned)(v & 0xffffffffull));
}
__device__ __forceinline__ float x2hi(unsigned long long v) {
    return __uint_as_float((unsigned)(v >> 32));
}

// ---------------- scratch ----------------
// fbuf slots (each S floats): 0=fo0 1=fs0 2=fo1 3=fs1 4=fo2 5=fs2
__device__ float d_fbuf[(size_t)6 * NN * HID];
__device__ __align__(16) __half d_gh[(size_t)4 * NN * HID];
__device__ float d_dinv[2 * NN];
__device__ int   d_cnt [2 * NN];
__device__ int   d_cur [2 * NN];
__device__ int   d_rs  [2 * (NN + 1)];
__device__ int   d_csr [2 * NE];
__device__ float d_weff[16384];   // tail layer-1 effective weights, interleaved [kp][c][2]

// ---------------- degree histogram ----------------
__global__ void count_k(const int4* __restrict__ d0, const int4* __restrict__ d1,
                        int* __restrict__ cnt, int ne4) {
    int i = blockIdx.x * blockDim.x + threadIdx.x;
    if (i >= 2 * ne4) return;
    int b = (i >= ne4) ? 1 : 0;
    int4 v = b ? d1[i - ne4] : d0[i];
    int* c = cnt + b * NN;
    atomicAdd(&c[v.x], 1);
    atomicAdd(&c[v.y], 1);
    atomicAdd(&c[v.z], 1);
    atomicAdd(&c[v.w], 1);
}

// ---------------- exclusive scan + dinv + cur init ----------------
__global__ void scan_k(const int* __restrict__ cntA, int* __restrict__ rsA,
                       float* __restrict__ dvA, int* __restrict__ curA, int n) {
    const int* cnt = cntA + blockIdx.x * NN;
    int*       rs  = rsA  + blockIdx.x * (NN + 1);
    float*     dv  = dvA  + blockIdx.x * NN;
    int*       cur = curA + blockIdx.x * NN;
    __shared__ int wsum[32];
    __shared__ int carry_s;
    int tid = threadIdx.x, lane = tid & 31, wid = tid >> 5;
    if (tid == 0) carry_s = 0;
    __syncthreads();
    for (int base = 0; base < n; base += 1024) {
        int i = base + tid;
        int v = (i < n) ? cnt[i] : 0;
        int x = v;
        #pragma unroll
        for (int d = 1; d < 32; d <<= 1) {
            int t = __shfl_up_sync(0xffffffffu, x, d);
            if (lane >= d) x += t;
        }
        if (lane == 31) wsum[wid] = x;
        __syncthreads();
        if (wid == 0) {
            int w = wsum[lane];
            int y = w;
            #pragma unroll
            for (int d = 1; d < 32; d <<= 1) {
                int t = __shfl_up_sync(0xffffffffu, y, d);
                if (lane >= d) y += t;
            }
            wsum[lane] = y - w;
        }
        __syncthreads();
        int excl = x - v + wsum[wid] + carry_s;
        if (i < n) {
            rs[i]  = excl;
            cur[i] = excl;
            dv[i]  = rsqrtf((float)(v > 0 ? v : 1));
        }
        __syncthreads();
        if (tid == 1023) carry_s = excl + v;
        __syncthreads();
    }
    if (threadIdx.x == 0) rs[n] = carry_s;
}

// ---------------- CSR fill ----------------
__global__ void fill_k(const int4* __restrict__ s0, const int4* __restrict__ s1,
                       const int4* __restrict__ d0, const int4* __restrict__ d1,
                       int* __restrict__ cur, int* __restrict__ csr, int ne4) {
    int i = blockIdx.x * blockDim.x + threadIdx.x;
    if (i >= 2 * ne4) return;
    int b = (i >= ne4) ? 1 : 0;
    int j = i - b * ne4;
    int4 dd = b ? d1[j] : d0[j];
    int4 sv = b ? s1[j] : s0[j];
    int* cu = cur + b * NN;
    int* cs = csr + (size_t)b * NE;
    cs[atomicAdd(&cu[dd.x], 1)] = sv.x;
    cs[atomicAdd(&cu[dd.y], 1)] = sv.y;
    cs[atomicAdd(&cu[dd.z], 1)] = sv.z;
    cs[atomicAdd(&cu[dd.w], 1)] = sv.w;
}

// ---------------- input GEMM + relu (H only; input-only deps) ----------------
// 64 nodes/block, 256 thr; thread: 4 nodes x 4 cols (cp, cp+16, cp+32, cp+48).
// Half-warp duplicated cols -> every w LDS.64 moves 128B = 1 crossbar cycle.
__global__ void gemm_relu_k(const float* __restrict__ X0, const float* __restrict__ X1,
                            const float* __restrict__ W0g, const float* __restrict__ W1g,
                            const float* __restrict__ b0, const float* __restrict__ b1,
                            float* __restrict__ f0base, int n) {
    __shared__ float Xs[64 * 128];   // 32 KB
    __shared__ float Wpc[4096];      // 16 KB [32kp][64c][2]
    int by = blockIdx.y;
    const float* X = by ? X1 : X0;
    const float* W = by ? W1g : W0g;
    const float* b = by ? b1 : b0;
    float* H = f0base + (size_t)by * S;

    int tid = threadIdx.x;
    int cp = tid & 15;        // col base (cols cp + 16q)
    int ng = tid >> 4;        // node group 0..15 (4 nodes each)
    int nb = blockIdx.x * 64;

    int limf = (n - nb) * 128;
    if (limf > 8192) limf = 8192;
    for (int i4 = tid; i4 < 2048; i4 += 256) {
        float4 v = make_float4(0.f, 0.f, 0.f, 0.f);
        if (i4 * 4 < limf) v = ((const float4*)(X + (size_t)nb * 128))[i4];
        ((float4*)Xs)[i4] = v;
    }

    unsigned long long acc[4][4];
    #pragma unroll
    for (int j = 0; j < 4; j++)
        #pragma unroll
        for (int q = 0; q < 4; q++) acc[j][q] = 0ull;

    #pragma unroll
    for (int ch = 0; ch < 2; ch++) {
        __syncthreads();
        for (int i = tid; i < 4096; i += 256) {
            int j = i & 1, c = (i >> 1) & 63, kp = i >> 7;
            Wpc[i] = W[(size_t)(ch * 64 + 2 * kp + j) * 64 + c];
        }
        __syncthreads();
        #pragma unroll 4
        for (int kp = 0; kp < 32; kp++) {
            unsigned long long w[4];
            #pragma unroll
            for (int q = 0; q < 4; q++)
                w[q] = *(const unsigned long long*)&Wpc[(kp * 64 + cp + 16 * q) * 2];
            #pragma unroll
            for (int j = 0; j < 4; j++) {
                unsigned long long x =
                    *(const unsigned long long*)&Xs[(ng * 4 + j) * 128 + ch * 64 + 2 * kp];
                #pragma unroll
                for (int q = 0; q < 4; q++) FMA_F32X2(acc[j][q], x, w[q], acc[j][q]);
            }
        }
    }

    #pragma unroll
    for (int j = 0; j < 4; j++) {
        int node = nb + ng * 4 + j;
        if (node < n) {
            #pragma unroll
            for (int q = 0; q < 4; q++) {
                int col = cp + 16 * q;
                float v = x2lo(acc[j][q]) + x2hi(acc[j][q]) + b[col];
                H[(size_t)node * 64 + col] = v > 0.f ? v : 0.f;
            }
        }
    }
}

// ---------------- g(fp16) = H * dinv (both branches) ----------------
__global__ void scale_k(const float4* __restrict__ H, const float* __restrict__ dinv_all,
                        uint4* __restrict__ G, int total) {   // total = 2*S/8
    int i = blockIdx.x * blockDim.x + threadIdx.x;
    if (i >= total) return;
    float dv = dinv_all[i >> 3];
    float4 a = H[2 * i], b = H[2 * i + 1];
    __half2 h0 = __floats2half2_rn(a.x * dv, a.y * dv);
    __half2 h1 = __floats2half2_rn(a.z * dv, a.w * dv);
    __half2 h2 = __floats2half2_rn(b.x * dv, b.y * dv);
    __half2 h3 = __floats2half2_rn(b.z * dv, b.w * dv);
    uint4 o;
    o.x = *(unsigned*)&h0; o.y = *(unsigned*)&h1;
    o.z = *(unsigned*)&h2; o.w = *(unsigned*)&h3;
    G[i] = o;
}

// ---------------- tail weight prep (combine-fold, interleaved) ----------------
__global__ void prep_k(const float* __restrict__ Wm1, float* __restrict__ weff) {
    int i = blockIdx.x * blockDim.x + threadIdx.x;
    if (i >= 16384) return;
    int j = i & 1, c = (i >> 1) & 63, kp = i >> 7;
    int r = 2 * kp + j;
    int s = r >> 6, kk = r & 63;
    float w0 = Wm1[kk * 64 + c];
    float w1 = Wm1[(64 + kk) * 64 + c];
    float w2 = Wm1[(128 + kk) * 64 + c];
    float v;
    if (s == 0)      v = 3.f * w0;
    else if (s == 1) v = -3.f * w0 + 3.f * w1;
    else if (s == 2) v = 0.75f * w0 - 1.5f * w1 + 0.75f * w2;
    else v = 4.f * (Wm1[(192 + kk) * 64 + c] + Wm1[(256 + kk) * 64 + c] +
                    Wm1[(320 + kk) * 64 + c]);
    weff[i] = v;
}

// ---------------- propagation: 4 edges in flight via 8-lane groups ----------------
__global__ void prop_k(const __half* __restrict__ gin, const float* __restrict__ fin,
                       float* __restrict__ fout, __half* __restrict__ gout,
                       const float* __restrict__ dinv_all, const int* __restrict__ rs_all,
                       const int* __restrict__ csr_all, int n, int writeG) {
    int gw = (blockIdx.x * blockDim.x + threadIdx.x) >> 5;
    int lane = threadIdx.x & 31;
    if (gw >= 2 * n) return;
    int b = (gw >= n) ? 1 : 0;
    int w = gw - b * n;
    const __half* gp  = gin + (size_t)b * S;
    const int*    rs  = rs_all + b * (NN + 1);
    const int*    csr = csr_all + (size_t)b * NE;
    int beg = rs[w], end = rs[w + 1];

    int grp = lane >> 3;
    int sub = lane & 7;

    float a[8];
    #pragma unroll
    for (int i = 0; i < 8; i++) a[i] = 0.f;

    for (int base = beg; base < end; base += 32) {
        int idx = base + lane;
        int sreg = (idx < end) ? __ldg(&csr[idx]) : 0;
        int cnt = end - base;
        if (cnt > 32) cnt = 32;
        #pragma unroll
        for (int tb = 0; tb < 8; tb++) {
            if (tb * 4 >= cnt) break;
            int t = tb * 4 + grp;
            int ss = __shfl_sync(0xffffffffu, sreg, t);
            if (t < cnt) {
                uint4 v = *(const uint4*)(gp + (size_t)ss * 64 + sub * 8);
                const __half2* h = (const __half2*)&v;
                #pragma unroll
                for (int q = 0; q < 4; q++) {
                    float2 f = __half22float2(h[q]);
                    a[2 * q]     += f.x;
                    a[2 * q + 1] += f.y;
                }
            }
        }
    }

    #pragma unroll
    for (int i = 0; i < 8; i++) {
        a[i] += __shfl_xor_sync(0xffffffffu, a[i], 8);
        a[i] += __shfl_xor_sync(0xffffffffu, a[i], 16);
    }

    if (lane < 8) {
        float dvv = dinv_all[b * NN + w];
        const float4* f4 = (const float4*)(fin + (size_t)b * S + (size_t)w * 64 + lane * 8);
        float4 fv0 = f4[0], fv1 = f4[1];
        float4 o0, o1;
        o0.x = fv0.x - a[0] * dvv;
        o0.y = fv0.y - a[1] * dvv;
        o0.z = fv0.z - a[2] * dvv;
        o0.w = fv0.w - a[3] * dvv;
        o1.x = fv1.x - a[4] * dvv;
        o1.y = fv1.y - a[5] * dvv;
        o1.z = fv1.z - a[6] * dvv;
        o1.w = fv1.w - a[7] * dvv;
        float4* fo = (float4*)(fout + (size_t)b * S + (size_t)w * 64 + lane * 8);
        fo[0] = o0;
        fo[1] = o1;
        if (writeG) {
            __half2 h0 = __floats2half2_rn(o0.x * dvv, o0.y * dvv);
            __half2 h1 = __floats2half2_rn(o0.z * dvv, o0.w * dvv);
            __half2 h2 = __floats2half2_rn(o1.x * dvv, o1.y * dvv);
            __half2 h3 = __floats2half2_rn(o1.z * dvv, o1.w * dvv);
            uint4 gv;
            gv.x = *(unsigned*)&h0; gv.y = *(unsigned*)&h1;
            gv.z = *(unsigned*)&h2; gv.w = *(unsigned*)&h3;
            *(uint4*)(gout + (size_t)b * S + (size_t)w * 64 + lane * 8) = gv;
        }
    }
}

// ---------------- fused tail: combine -> h_all + 2-layer MLP ----------------
// 32 nodes/block, 128 thr; thread: 4 nodes x 4 cols.
__global__ void tail_k(const float* __restrict__ fbuf, const float* __restrict__ weffp,
                       const float* __restrict__ bm1, const float* __restrict__ Wm2,
                       const float* __restrict__ bm2,
                       float* __restrict__ out, float* __restrict__ logits, int n) {
    __shared__ float Xs[4][32 * 64];   // 32 KB
    __shared__ float Wpc[4096];        // 16 KB
    __shared__ float Zs[32 * 68];      // 8.5 KB
    int tid = threadIdx.x;
    int cp = tid & 15, ng = tid >> 4;  // ng 0..7, 4 nodes each
    int nb = blockIdx.x * 32;

    const float* fo0 = fbuf + 0 * S;
    const float* fs0 = fbuf + 1 * S;
    const float* fo1 = fbuf + 2 * S;
    const float* fs1 = fbuf + 3 * S;
    const float* fo2 = fbuf + 4 * S;
    const float* fs2 = fbuf + 5 * S;

    // stage as float4 (512 float4 per array)
    int lim4 = (n - nb) * 16;
    if (lim4 > 512) lim4 = 512;
    for (int i4 = tid; i4 < 512; i4 += 128) {
        float4 z = make_float4(0.f, 0.f, 0.f, 0.f);
        float4 v0 = z, v1 = z, v2 = z, vs = z;
        if (i4 < lim4) {
            size_t off = (size_t)nb * 16 + i4;
            v0 = ((const float4*)fo0)[off];
            v1 = ((const float4*)fo1)[off];
            v2 = ((const float4*)fo2)[off];
            float4 u0 = ((const float4*)fs0)[off];
            float4 u1 = ((const float4*)fs1)[off];
            float4 u2 = ((const float4*)fs2)[off];
            vs.x = u0.x + u1.x + u2.x;
            vs.y = u0.y + u1.y + u2.y;
            vs.z = u0.z + u1.z + u2.z;
            vs.w = u0.w + u1.w + u2.w;
        }
        ((float4*)Xs[0])[i4] = v0;
        ((float4*)Xs[1])[i4] = v1;
        ((float4*)Xs[2])[i4] = v2;
        ((float4*)Xs[3])[i4] = vs;
    }
    __syncthreads();

    // h_all write (float4): 32 nodes x 96 float4
    int limo4 = (n - nb) * 96;
    if (limo4 > 3072) limo4 = 3072;
    for (int i4 = tid; i4 < limo4; i4 += 128) {
        int node_l = i4 / 96;
        int c4 = i4 - node_l * 96;
        int seg = c4 >> 4, cc4 = c4 & 15;
        int xi4 = node_l * 16 + cc4;
        float4 v;
        if (seg == 0) {
            float4 a0 = ((const float4*)Xs[0])[xi4];
            float4 a1 = ((const float4*)Xs[1])[xi4];
            float4 a2 = ((const float4*)Xs[2])[xi4];
            v.x = 3.f * a0.x - 3.f * a1.x + 0.75f * a2.x;
            v.y = 3.f * a0.y - 3.f * a1.y + 0.75f * a2.y;
            v.z = 3.f * a0.z - 3.f * a1.z + 0.75f * a2.z;
            v.w = 3.f * a0.w - 3.f * a1.w + 0.75f * a2.w;
        } else if (seg == 1) {
            float4 a1 = ((const float4*)Xs[1])[xi4];
            float4 a2 = ((const float4*)Xs[2])[xi4];
            v.x = 3.f * a1.x - 1.5f * a2.x;
            v.y = 3.f * a1.y - 1.5f * a2.y;
            v.z = 3.f * a1.z - 1.5f * a2.z;
            v.w = 3.f * a1.w - 1.5f * a2.w;
        } else if (seg == 2) {
            float4 a2 = ((const float4*)Xs[2])[xi4];
            v.x = 0.75f * a2.x; v.y = 0.75f * a2.y;
            v.z = 0.75f * a2.z; v.w = 0.75f * a2.w;
        } else {
            float4 a3 = ((const float4*)Xs[3])[xi4];
            v.x = 4.f * a3.x; v.y = 4.f * a3.y;
            v.z = 4.f * a3.z; v.w = 4.f * a3.w;
        }
        ((float4*)(out + (size_t)nb * 384))[i4] = v;
    }

    // layer 1 (K = 4 x 64, effective weights)
    unsigned long long acc[4][4];
    #pragma unroll
    for (int j = 0; j < 4; j++)
        #pragma unroll
        for (int q = 0; q < 4; q++) acc[j][q] = 0ull;

    #pragma unroll
    for (int s = 0; s < 4; s++) {
        __syncthreads();
        for (int i = tid; i < 4096; i += 128) Wpc[i] = weffp[s * 4096 + i];
        __syncthreads();
        #pragma unroll 4
        for (int kp = 0; kp < 32; kp++) {
            unsigned long long w[4];
            #pragma unroll
            for (int q = 0; q < 4; q++)
                w[q] = *(const unsigned long long*)&Wpc[(kp * 64 + cp + 16 * q) * 2];
            #pragma unroll
            for (int j = 0; j < 4; j++) {
                unsigned long long x =
                    *(const unsigned long long*)&Xs[s][(ng * 4 + j) * 64 + 2 * kp];
                #pragma unroll
                for (int q = 0; q < 4; q++) FMA_F32X2(acc[j][q], x, w[q], acc[j][q]);
            }
        }
    }
    __syncthreads();
    #pragma unroll
    for (int j = 0; j < 4; j++) {
        int node_l = ng * 4 + j;
        #pragma unroll
        for (int q = 0; q < 4; q++) {
            int col = cp + 16 * q;
            float z = x2lo(acc[j][q]) + x2hi(acc[j][q]) + bm1[col];
            Zs[node_l * 68 + col] = z > 0.f ? z : 0.f;
        }
    }
    __syncthreads();

    // layer 2: 64 outputs (32 nodes x 2)
    if (tid < 64) {
        int node = tid >> 1, jj = tid & 1;
        if (nb + node < n) {
            float sacc = bm2[jj];
            #pragma unroll 8
            for (int c = 0; c < 64; c++) sacc += Zs[node * 68 + c] * Wm2[c * 2 + jj];
            logits[(size_t)(nb + node) * 2 + jj] = sacc;
        }
    }
}

// ---------------- launch ----------------
extern "C" void kernel_launch(void* const* d_in, const int* in_sizes, int n_in,
                              void* d_out, int out_size) {
    const float* x     = (const float*)d_in[0];
    const float* sim_x = (const float*)d_in[1];
    const int*   src   = (const int*)d_in[2];
    const int*   dst   = (const int*)d_in[3];
    const int*   ssrc  = (const int*)d_in[4];
    const int*   sdst  = (const int*)d_in[5];
    const float* W1o   = (const float*)d_in[6];
    const float* b1o   = (const float*)d_in[7];
    const float* W1s   = (const float*)d_in[8];
    const float* b1s   = (const float*)d_in[9];
    const float* Wm1   = (const float*)d_in[10];
    const float* bm1   = (const float*)d_in[11];
    const float* Wm2   = (const float*)d_in[12];
    const float* bm2   = (const float*)d_in[13];

    const int n = NN, ne = NE;

    float *fbuf, *dinv, *weff; __half* gh; int *cnt, *cur, *rs, *csr;
    cudaGetSymbolAddress((void**)&fbuf, d_fbuf);
    cudaGetSymbolAddress((void**)&gh,   d_gh);
    cudaGetSymbolAddress((void**)&dinv, d_dinv);
    cudaGetSymbolAddress((void**)&cnt,  d_cnt);
    cudaGetSymbolAddress((void**)&cur,  d_cur);
    cudaGetSymbolAddress((void**)&rs,   d_rs);
    cudaGetSymbolAddress((void**)&csr,  d_csr);
    cudaGetSymbolAddress((void**)&weff, d_weff);

    float*  f0base = fbuf + 0 * S;
    float*  f1base = fbuf + 2 * S;
    float*  f2base = fbuf + 4 * S;
    __half* gabase = gh;
    __half* gbbase = gh + 2 * S;

    static cudaStream_t sB = nullptr;
    static cudaEvent_t eStart = nullptr, eScan = nullptr, eB = nullptr;
    if (!sB) {
        cudaStreamCreateWithFlags(&sB, cudaStreamNonBlocking);
        cudaEventCreateWithFlags(&eStart, cudaEventDisableTiming);
        cudaEventCreateWithFlags(&eScan,  cudaEventDisableTiming);
        cudaEventCreateWithFlags(&eB,     cudaEventDisableTiming);
    }

    cudaEventRecord(eStart, 0);
    cudaStreamWaitEvent(sB, eStart, 0);

    // stream0: CSR build chain
    cudaMemsetAsync(cnt, 0, (size_t)2 * NN * sizeof(int), 0);
    int ne4 = ne / 4;
    int eb4 = (2 * ne4 + 255) / 256;
    count_k<<<eb4, 256>>>((const int4*)dst, (const int4*)sdst, cnt, ne4);
    scan_k<<<2, 1024>>>(cnt, rs, dinv, cur, n);
    cudaEventRecord(eScan, 0);
    fill_k<<<eb4, 256>>>((const int4*)src, (const int4*)ssrc,
                         (const int4*)dst, (const int4*)sdst, cur, csr, ne4);

    // sB: gemm from t0 (input-only deps), prep, then scale after scan
    dim3 gg((n + 63) / 64, 2);
    gemm_relu_k<<<gg, 256, 0, sB>>>(x, sim_x, W1o, W1s, b1o, b1s, f0base, n);
    prep_k<<<64, 256, 0, sB>>>(Wm1, weff);
    cudaStreamWaitEvent(sB, eScan, 0);
    int total8 = (int)(2 * S / 8);
    scale_k<<<(total8 + 255) / 256, 256, 0, sB>>>((const float4*)f0base, dinv,
                                                  (uint4*)gabase, total8);
    cudaEventRecord(eB, sB);

    // join, then serial props + tail on stream0
    cudaStreamWaitEvent(0, eB, 0);
    int pb = (2 * n * 32 + 255) / 256;
    prop_k<<<pb, 256>>>(gabase, f0base, f1base, gbbase, dinv, rs, csr, n, 1);
    prop_k<<<pb, 256>>>(gbbase, f1base, f2base, nullptr, dinv, rs, csr, n, 0);

    float* out    = (float*)d_out;
    float* logits = out + (size_t)n * 384;
    tail_k<<<(n + 31) / 32, 128>>>(fbuf, weff, bm1, Wm2, bm2, out, logits, n);
}

// round 11
// speedup vs baseline: 1.5847x; 1.1047x over previous
#include <cuda_runtime.h>
#include <cuda_bf16.h>
#include <cuda_fp16.h>
#include <stdint.h>

#define NN 50000
#define NE 800000
#define INF 128
#define HID 64
#define S ((size_t)NN * HID)

// packed dual fp32 FMA (sm_103a)
#define FMA_F32X2(d, a, b, c) \
    asm("fma.rn.f32x2 %0, %1, %2, %3;" : "=l"(d) : "l"(a), "l"(b), "l"(c))

__device__ __forceinline__ float x2lo(unsigned long long v) {
    return __uint_as_float((unsigned)(v & 0xffffffffull));
}
__device__ __forceinline__ float x2hi(unsigned long long v) {
    return __uint_as_float((unsigned)(v >> 32));
}

// ---------------- scratch ----------------
__device__ float d_fbuf[(size_t)6 * NN * HID];
__device__ __align__(16) __half d_gh[(size_t)4 * NN * HID];
__device__ float d_dinv[2 * NN];
__device__ int   d_cnt [2 * NN];
__device__ int   d_cur [2 * NN];
__device__ int   d_rs  [2 * (NN + 1)];
__device__ int   d_csr [2 * NE];
__device__ float d_weff[16384];   // tail layer-1 effective weights, interleaved [kp][c][2]

// ---------------- degree histogram ----------------
__global__ void count_k(const int4* __restrict__ d0, const int4* __restrict__ d1,
                        int* __restrict__ cnt, int ne4) {
    int i = blockIdx.x * blockDim.x + threadIdx.x;
    if (i >= 2 * ne4) return;
    int b = (i >= ne4) ? 1 : 0;
    int4 v = b ? d1[i - ne4] : d0[i];
    int* c = cnt + b * NN;
    atomicAdd(&c[v.x], 1);
    atomicAdd(&c[v.y], 1);
    atomicAdd(&c[v.z], 1);
    atomicAdd(&c[v.w], 1);
}

// ---------------- exclusive scan + dinv + cur init ----------------
__global__ void scan_k(const int* __restrict__ cntA, int* __restrict__ rsA,
                       float* __restrict__ dvA, int* __restrict__ curA, int n) {
    const int* cnt = cntA + blockIdx.x * NN;
    int*       rs  = rsA  + blockIdx.x * (NN + 1);
    float*     dv  = dvA  + blockIdx.x * NN;
    int*       cur = curA + blockIdx.x * NN;
    __shared__ int wsum[32];
    __shared__ int carry_s;
    int tid = threadIdx.x, lane = tid & 31, wid = tid >> 5;
    if (tid == 0) carry_s = 0;
    __syncthreads();
    for (int base = 0; base < n; base += 1024) {
        int i = base + tid;
        int v = (i < n) ? cnt[i] : 0;
        int x = v;
        #pragma unroll
        for (int d = 1; d < 32; d <<= 1) {
            int t = __shfl_up_sync(0xffffffffu, x, d);
            if (lane >= d) x += t;
        }
        if (lane == 31) wsum[wid] = x;
        __syncthreads();
        if (wid == 0) {
            int w = wsum[lane];
            int y = w;
            #pragma unroll
            for (int d = 1; d < 32; d <<= 1) {
                int t = __shfl_up_sync(0xffffffffu, y, d);
                if (lane >= d) y += t;
            }
            wsum[lane] = y - w;
        }
        __syncthreads();
        int excl = x - v + wsum[wid] + carry_s;
        if (i < n) {
            rs[i]  = excl;
            cur[i] = excl;
            dv[i]  = rsqrtf((float)(v > 0 ? v : 1));
        }
        __syncthreads();
        if (tid == 1023) carry_s = excl + v;
        __syncthreads();
    }
    if (threadIdx.x == 0) rs[n] = carry_s;
}

// ---------------- CSR fill ----------------
__global__ void fill_k(const int4* __restrict__ s0, const int4* __restrict__ s1,
                       const int4* __restrict__ d0, const int4* __restrict__ d1,
                       int* __restrict__ cur, int* __restrict__ csr, int ne4) {
    int i = blockIdx.x * blockDim.x + threadIdx.x;
    if (i >= 2 * ne4) return;
    int b = (i >= ne4) ? 1 : 0;
    int j = i - b * ne4;
    int4 dd = b ? d1[j] : d0[j];
    int4 sv = b ? s1[j] : s0[j];
    int* cu = cur + b * NN;
    int* cs = csr + (size_t)b * NE;
    cs[atomicAdd(&cu[dd.x], 1)] = sv.x;
    cs[atomicAdd(&cu[dd.y], 1)] = sv.y;
    cs[atomicAdd(&cu[dd.z], 1)] = sv.z;
    cs[atomicAdd(&cu[dd.w], 1)] = sv.w;
}

// ---------------- input GEMM + relu (chunked Xs stage; 33KB smem) ----------------
// 64 nodes/block, 256 thr; thread: 4 nodes x 4 cols (cp + 16q).
__global__ void __launch_bounds__(256) gemm_relu_k(
        const float* __restrict__ X0, const float* __restrict__ X1,
        const float* __restrict__ W0g, const float* __restrict__ W1g,
        const float* __restrict__ b0, const float* __restrict__ b1,
        float* __restrict__ f0base, int n) {
    __shared__ float Xs[64 * 64];    // 16 KB (one 64-k chunk)
    __shared__ float Wpc[4096];      // 16 KB [32kp][64c][2]
    int by = blockIdx.y;
    const float* X = by ? X1 : X0;
    const float* W = by ? W1g : W0g;
    const float* b = by ? b1 : b0;
    float* H = f0base + (size_t)by * S;

    int tid = threadIdx.x;
    int cp = tid & 15;
    int ng = tid >> 4;        // 0..15, 4 nodes each
    int nb = blockIdx.x * 64;
    int nvalid = n - nb; if (nvalid > 64) nvalid = 64;

    unsigned long long acc[4][4];
    #pragma unroll
    for (int j = 0; j < 4; j++)
        #pragma unroll
        for (int q = 0; q < 4; q++) acc[j][q] = 0ull;

    #pragma unroll
    for (int ch = 0; ch < 2; ch++) {
        __syncthreads();
        // stage X chunk: 64 nodes x 16 float4 (k in [ch*64, ch*64+64))
        for (int i4 = tid; i4 < 1024; i4 += 256) {
            int node = i4 >> 4, f = i4 & 15;
            float4 v = make_float4(0.f, 0.f, 0.f, 0.f);
            if (node < nvalid)
                v = *(const float4*)(X + (size_t)(nb + node) * 128 + ch * 64 + f * 4);
            ((float4*)Xs)[i4] = v;
        }
        // stage W chunk interleaved
        for (int i = tid; i < 4096; i += 256) {
            int j = i & 1, c = (i >> 1) & 63, kp = i >> 7;
            Wpc[i] = W[(size_t)(ch * 64 + 2 * kp + j) * 64 + c];
        }
        __syncthreads();
        #pragma unroll 4
        for (int kp2 = 0; kp2 < 16; kp2++) {
            float4 x4[4];
            #pragma unroll
            for (int j = 0; j < 4; j++)
                x4[j] = *(const float4*)&Xs[(ng * 4 + j) * 64 + 4 * kp2];
            #pragma unroll
            for (int h = 0; h < 2; h++) {
                int kp = 2 * kp2 + h;
                unsigned long long w[4];
                #pragma unroll
                for (int q = 0; q < 4; q++)
                    w[q] = *(const unsigned long long*)&Wpc[(kp * 64 + cp + 16 * q) * 2];
                #pragma unroll
                for (int j = 0; j < 4; j++) {
                    unsigned long long x = ((const unsigned long long*)&x4[j])[h];
                    #pragma unroll
                    for (int q = 0; q < 4; q++) FMA_F32X2(acc[j][q], x, w[q], acc[j][q]);
                }
            }
        }
    }

    #pragma unroll
    for (int j = 0; j < 4; j++) {
        int node = nb + ng * 4 + j;
        if (node < n) {
            #pragma unroll
            for (int q = 0; q < 4; q++) {
                int col = cp + 16 * q;
                float v = x2lo(acc[j][q]) + x2hi(acc[j][q]) + b[col];
                H[(size_t)node * 64 + col] = v > 0.f ? v : 0.f;
            }
        }
    }
}

// ---------------- g(fp16) = H * dinv ----------------
__global__ void scale_k(const float4* __restrict__ H, const float* __restrict__ dinv_all,
                        uint4* __restrict__ G, int total) {
    int i = blockIdx.x * blockDim.x + threadIdx.x;
    if (i >= total) return;
    float dv = dinv_all[i >> 3];
    float4 a = H[2 * i], b = H[2 * i + 1];
    __half2 h0 = __floats2half2_rn(a.x * dv, a.y * dv);
    __half2 h1 = __floats2half2_rn(a.z * dv, a.w * dv);
    __half2 h2 = __floats2half2_rn(b.x * dv, b.y * dv);
    __half2 h3 = __floats2half2_rn(b.z * dv, b.w * dv);
    uint4 o;
    o.x = *(unsigned*)&h0; o.y = *(unsigned*)&h1;
    o.z = *(unsigned*)&h2; o.w = *(unsigned*)&h3;
    G[i] = o;
}

// ---------------- tail weight prep ----------------
__global__ void prep_k(const float* __restrict__ Wm1, float* __restrict__ weff) {
    int i = blockIdx.x * blockDim.x + threadIdx.x;
    if (i >= 16384) return;
    int j = i & 1, c = (i >> 1) & 63, kp = i >> 7;
    int r = 2 * kp + j;
    int s = r >> 6, kk = r & 63;
    float w0 = Wm1[kk * 64 + c];
    float w1 = Wm1[(64 + kk) * 64 + c];
    float w2 = Wm1[(128 + kk) * 64 + c];
    float v;
    if (s == 0)      v = 3.f * w0;
    else if (s == 1) v = -3.f * w0 + 3.f * w1;
    else if (s == 2) v = 0.75f * w0 - 1.5f * w1 + 0.75f * w2;
    else v = 4.f * (Wm1[(192 + kk) * 64 + c] + Wm1[(256 + kk) * 64 + c] +
                    Wm1[(320 + kk) * 64 + c]);
    weff[i] = v;
}

// ---------------- propagation: 4 edges in flight via 8-lane groups ----------------
__global__ void prop_k(const __half* __restrict__ gin, const float* __restrict__ fin,
                       float* __restrict__ fout, __half* __restrict__ gout,
                       const float* __restrict__ dinv_all, const int* __restrict__ rs_all,
                       const int* __restrict__ csr_all, int n, int writeG) {
    int gw = (blockIdx.x * blockDim.x + threadIdx.x) >> 5;
    int lane = threadIdx.x & 31;
    if (gw >= 2 * n) return;
    int b = (gw >= n) ? 1 : 0;
    int w = gw - b * n;
    const __half* gp  = gin + (size_t)b * S;
    const int*    rs  = rs_all + b * (NN + 1);
    const int*    csr = csr_all + (size_t)b * NE;
    int beg = rs[w], end = rs[w + 1];

    int grp = lane >> 3;
    int sub = lane & 7;

    float a[8];
    #pragma unroll
    for (int i = 0; i < 8; i++) a[i] = 0.f;

    for (int base = beg; base < end; base += 32) {
        int idx = base + lane;
        int sreg = (idx < end) ? __ldg(&csr[idx]) : 0;
        int cnt = end - base;
        if (cnt > 32) cnt = 32;
        #pragma unroll
        for (int tb = 0; tb < 8; tb++) {
            if (tb * 4 >= cnt) break;
            int t = tb * 4 + grp;
            int ss = __shfl_sync(0xffffffffu, sreg, t);
            if (t < cnt) {
                uint4 v = *(const uint4*)(gp + (size_t)ss * 64 + sub * 8);
                const __half2* h = (const __half2*)&v;
                #pragma unroll
                for (int q = 0; q < 4; q++) {
                    float2 f = __half22float2(h[q]);
                    a[2 * q]     += f.x;
                    a[2 * q + 1] += f.y;
                }
            }
        }
    }

    #pragma unroll
    for (int i = 0; i < 8; i++) {
        a[i] += __shfl_xor_sync(0xffffffffu, a[i], 8);
        a[i] += __shfl_xor_sync(0xffffffffu, a[i], 16);
    }

    if (lane < 8) {
        float dvv = dinv_all[b * NN + w];
        const float4* f4 = (const float4*)(fin + (size_t)b * S + (size_t)w * 64 + lane * 8);
        float4 fv0 = f4[0], fv1 = f4[1];
        float4 o0, o1;
        o0.x = fv0.x - a[0] * dvv;
        o0.y = fv0.y - a[1] * dvv;
        o0.z = fv0.z - a[2] * dvv;
        o0.w = fv0.w - a[3] * dvv;
        o1.x = fv1.x - a[4] * dvv;
        o1.y = fv1.y - a[5] * dvv;
        o1.z = fv1.z - a[6] * dvv;
        o1.w = fv1.w - a[7] * dvv;
        float4* fo = (float4*)(fout + (size_t)b * S + (size_t)w * 64 + lane * 8);
        fo[0] = o0;
        fo[1] = o1;
        if (writeG) {
            __half2 h0 = __floats2half2_rn(o0.x * dvv, o0.y * dvv);
            __half2 h1 = __floats2half2_rn(o0.z * dvv, o0.w * dvv);
            __half2 h2 = __floats2half2_rn(o1.x * dvv, o1.y * dvv);
            __half2 h3 = __floats2half2_rn(o1.z * dvv, o1.w * dvv);
            uint4 gv;
            gv.x = *(unsigned*)&h0; gv.y = *(unsigned*)&h1;
            gv.z = *(unsigned*)&h2; gv.w = *(unsigned*)&h3;
            *(uint4*)(gout + (size_t)b * S + (size_t)w * 64 + lane * 8) = gv;
        }
    }
}

// ---------------- fused tail: combine -> h_all + 2-layer MLP ----------------
// 32 nodes/block, 256 thr; thread: 2 nodes x 4 cols.
__global__ void __launch_bounds__(256) tail_k(
        const float* __restrict__ fbuf, const float* __restrict__ weffp,
        const float* __restrict__ bm1, const float* __restrict__ Wm2,
        const float* __restrict__ bm2,
        float* __restrict__ out, float* __restrict__ logits, int n) {
    __shared__ float Xs[4][32 * 64];   // 32 KB
    __shared__ float Wpc[4096];        // 16 KB
    __shared__ float Zs[32 * 68];      // 8.5 KB
    int tid = threadIdx.x;
    int cp = tid & 15, ng = tid >> 4;  // ng 0..15, 2 nodes each
    int nb = blockIdx.x * 32;

    const float* fo0 = fbuf + 0 * S;
    const float* fs0 = fbuf + 1 * S;
    const float* fo1 = fbuf + 2 * S;
    const float* fs1 = fbuf + 3 * S;
    const float* fo2 = fbuf + 4 * S;
    const float* fs2 = fbuf + 5 * S;

    int lim4 = (n - nb) * 16;
    if (lim4 > 512) lim4 = 512;
    for (int i4 = tid; i4 < 512; i4 += 256) {
        float4 z = make_float4(0.f, 0.f, 0.f, 0.f);
        float4 v0 = z, v1 = z, v2 = z, vs = z;
        if (i4 < lim4) {
            size_t off = (size_t)nb * 16 + i4;
            v0 = ((const float4*)fo0)[off];
            v1 = ((const float4*)fo1)[off];
            v2 = ((const float4*)fo2)[off];
            float4 u0 = ((const float4*)fs0)[off];
            float4 u1 = ((const float4*)fs1)[off];
            float4 u2 = ((const float4*)fs2)[off];
            vs.x = u0.x + u1.x + u2.x;
            vs.y = u0.y + u1.y + u2.y;
            vs.z = u0.z + u1.z + u2.z;
            vs.w = u0.w + u1.w + u2.w;
        }
        ((float4*)Xs[0])[i4] = v0;
        ((float4*)Xs[1])[i4] = v1;
        ((float4*)Xs[2])[i4] = v2;
        ((float4*)Xs[3])[i4] = vs;
    }
    __syncthreads();

    // h_all write (float4): 32 nodes x 96 float4
    int limo4 = (n - nb) * 96;
    if (limo4 > 3072) limo4 = 3072;
    for (int i4 = tid; i4 < limo4; i4 += 256) {
        int node_l = i4 / 96;
        int c4 = i4 - node_l * 96;
        int seg = c4 >> 4, cc4 = c4 & 15;
        int xi4 = node_l * 16 + cc4;
        float4 v;
        if (seg == 0) {
            float4 a0 = ((const float4*)Xs[0])[xi4];
            float4 a1 = ((const float4*)Xs[1])[xi4];
            float4 a2 = ((const float4*)Xs[2])[xi4];
            v.x = 3.f * a0.x - 3.f * a1.x + 0.75f * a2.x;
            v.y = 3.f * a0.y - 3.f * a1.y + 0.75f * a2.y;
            v.z = 3.f * a0.z - 3.f * a1.z + 0.75f * a2.z;
            v.w = 3.f * a0.w - 3.f * a1.w + 0.75f * a2.w;
        } else if (seg == 1) {
            float4 a1 = ((const float4*)Xs[1])[xi4];
            float4 a2 = ((const float4*)Xs[2])[xi4];
            v.x = 3.f * a1.x - 1.5f * a2.x;
            v.y = 3.f * a1.y - 1.5f * a2.y;
            v.z = 3.f * a1.z - 1.5f * a2.z;
            v.w = 3.f * a1.w - 1.5f * a2.w;
        } else if (seg == 2) {
            float4 a2 = ((const float4*)Xs[2])[xi4];
            v.x = 0.75f * a2.x; v.y = 0.75f * a2.y;
            v.z = 0.75f * a2.z; v.w = 0.75f * a2.w;
        } else {
            float4 a3 = ((const float4*)Xs[3])[xi4];
            v.x = 4.f * a3.x; v.y = 4.f * a3.y;
            v.z = 4.f * a3.z; v.w = 4.f * a3.w;
        }
        ((float4*)(out + (size_t)nb * 384))[i4] = v;
    }

    // layer 1 (K = 4 x 64, effective weights)
    unsigned long long acc[2][4];
    #pragma unroll
    for (int j = 0; j < 2; j++)
        #pragma unroll
        for (int q = 0; q < 4; q++) acc[j][q] = 0ull;

    #pragma unroll
    for (int s = 0; s < 4; s++) {
        __syncthreads();
        for (int i = tid; i < 4096; i += 256) Wpc[i] = weffp[s * 4096 + i];
        __syncthreads();
        #pragma unroll 4
        for (int kp2 = 0; kp2 < 16; kp2++) {
            float4 x4[2];
            #pragma unroll
            for (int j = 0; j < 2; j++)
                x4[j] = *(const float4*)&Xs[s][(ng * 2 + j) * 64 + 4 * kp2];
            #pragma unroll
            for (int h = 0; h < 2; h++) {
                int kp = 2 * kp2 + h;
                unsigned long long w[4];
                #pragma unroll
                for (int q = 0; q < 4; q++)
                    w[q] = *(const unsigned long long*)&Wpc[(kp * 64 + cp + 16 * q) * 2];
                #pragma unroll
                for (int j = 0; j < 2; j++) {
                    unsigned long long x = ((const unsigned long long*)&x4[j])[h];
                    #pragma unroll
                    for (int q = 0; q < 4; q++) FMA_F32X2(acc[j][q], x, w[q], acc[j][q]);
                }
            }
        }
    }
    __syncthreads();
    #pragma unroll
    for (int j = 0; j < 2; j++) {
        int node_l = ng * 2 + j;
        #pragma unroll
        for (int q = 0; q < 4; q++) {
            int col = cp + 16 * q;
            float z = x2lo(acc[j][q]) + x2hi(acc[j][q]) + bm1[col];
            Zs[node_l * 68 + col] = z > 0.f ? z : 0.f;
        }
    }
    __syncthreads();

    // layer 2: 64 outputs (32 nodes x 2)
    if (tid < 64) {
        int node = tid >> 1, jj = tid & 1;
        if (nb + node < n) {
            float sacc = bm2[jj];
            #pragma unroll 8
            for (int c = 0; c < 64; c++) sacc += Zs[node * 68 + c] * Wm2[c * 2 + jj];
            logits[(size_t)(nb + node) * 2 + jj] = sacc;
        }
    }
}

// ---------------- launch ----------------
extern "C" void kernel_launch(void* const* d_in, const int* in_sizes, int n_in,
                              void* d_out, int out_size) {
    const float* x     = (const float*)d_in[0];
    const float* sim_x = (const float*)d_in[1];
    const int*   src   = (const int*)d_in[2];
    const int*   dst   = (const int*)d_in[3];
    const int*   ssrc  = (const int*)d_in[4];
    const int*   sdst  = (const int*)d_in[5];
    const float* W1o   = (const float*)d_in[6];
    const float* b1o   = (const float*)d_in[7];
    const float* W1s   = (const float*)d_in[8];
    const float* b1s   = (const float*)d_in[9];
    const float* Wm1   = (const float*)d_in[10];
    const float* bm1   = (const float*)d_in[11];
    const float* Wm2   = (const float*)d_in[12];
    const float* bm2   = (const float*)d_in[13];

    const int n = NN, ne = NE;

    float *fbuf, *dinv, *weff; __half* gh; int *cnt, *cur, *rs, *csr;
    cudaGetSymbolAddress((void**)&fbuf, d_fbuf);
    cudaGetSymbolAddress((void**)&gh,   d_gh);
    cudaGetSymbolAddress((void**)&dinv, d_dinv);
    cudaGetSymbolAddress((void**)&cnt,  d_cnt);
    cudaGetSymbolAddress((void**)&cur,  d_cur);
    cudaGetSymbolAddress((void**)&rs,   d_rs);
    cudaGetSymbolAddress((void**)&csr,  d_csr);
    cudaGetSymbolAddress((void**)&weff, d_weff);

    float*  f0base = fbuf + 0 * S;
    float*  f1base = fbuf + 2 * S;
    float*  f2base = fbuf + 4 * S;
    __half* gabase = gh;
    __half* gbbase = gh + 2 * S;

    static cudaStream_t sB = nullptr;
    static cudaEvent_t eStart = nullptr, eScan = nullptr, eB = nullptr;
    if (!sB) {
        cudaStreamCreateWithFlags(&sB, cudaStreamNonBlocking);
        cudaEventCreateWithFlags(&eStart, cudaEventDisableTiming);
        cudaEventCreateWithFlags(&eScan,  cudaEventDisableTiming);
        cudaEventCreateWithFlags(&eB,     cudaEventDisableTiming);
    }

    cudaEventRecord(eStart, 0);
    cudaStreamWaitEvent(sB, eStart, 0);

    // stream0: CSR build chain
    cudaMemsetAsync(cnt, 0, (size_t)2 * NN * sizeof(int), 0);
    int ne4 = ne / 4;
    int eb4 = (2 * ne4 + 255) / 256;
    count_k<<<eb4, 256>>>((const int4*)dst, (const int4*)sdst, cnt, ne4);
    scan_k<<<2, 1024>>>(cnt, rs, dinv, cur, n);
    cudaEventRecord(eScan, 0);
    fill_k<<<eb4, 256>>>((const int4*)src, (const int4*)ssrc,
                         (const int4*)dst, (const int4*)sdst, cur, csr, ne4);

    // sB: gemm from t0 (input-only deps), prep, then scale after scan
    dim3 gg((n + 63) / 64, 2);
    gemm_relu_k<<<gg, 256, 0, sB>>>(x, sim_x, W1o, W1s, b1o, b1s, f0base, n);
    prep_k<<<64, 256, 0, sB>>>(Wm1, weff);
    cudaStreamWaitEvent(sB, eScan, 0);
    int total8 = (int)(2 * S / 8);
    scale_k<<<(total8 + 255) / 256, 256, 0, sB>>>((const float4*)f0base, dinv,
                                                  (uint4*)gabase, total8);
    cudaEventRecord(eB, sB);

    // join, then serial props + tail on stream0
    cudaStreamWaitEvent(0, eB, 0);
    int pb = (2 * n * 32 + 255) / 256;
    prop_k<<<pb, 256>>>(gabase, f0base, f1base, gbbase, dinv, rs, csr, n, 1);
    prop_k<<<pb, 256>>>(gbbase, f1base, f2base, nullptr, dinv, rs, csr, n, 0);

    float* out    = (float*)d_out;
    float* logits = out + (size_t)n * 384;
    tail_k<<<(n + 31) / 32, 256>>>(fbuf, weff, bm1, Wm2, bm2, out, logits, n);
}